// round 6
// baseline (speedup 1.0000x reference)
#include <cuda_runtime.h>
#include <cuda_fp16.h>
#include <math.h>
#include <stdint.h>

#define B_  8
#define N_  16384
#define C_  256
#define M_  (B_*N_)      // 131072 rows
#define MC_ ((size_t)M_*C_)
#define L_  128          // scan chunk length
#define NC_ (N_/L_)      // 128 chunks per batch

// ---- GEMM tiling ----
#define BM 128
#define BN 64
#define KCH 64
#define NKC (C_/KCH)           // 4
#define SAS 72                 // smem row stride in halves (144B)
#define A_B (BM*SAS*2)
#define B_B (BN*SAS*2)
#define STAGE_B (A_B + B_B)
#define SMEM_REQ (2*STAGE_B)   // 55296

// ---- scratch ----
__device__ __half g_kvr[3*MC_];        // k, v, r  (fp16)
__device__ __half g_xa[MC_];           // LN(x) fp16
__device__ __half g_ya[MC_];           // y fp16
__device__ __half g_Wa[3*C_*C_];       // Wk,Wv,Wr fp16
__device__ __half g_Woa[C_*C_];        // Wo fp16
__device__ float  g_incl[B_*NC_*C_];   // inclusive chunk-end states
__device__ int    g_flag[B_*NC_];      // ready flags

// ============================================================
// helpers
// ============================================================
__device__ __forceinline__ uint32_t smem_u32(const void* p) {
    return (uint32_t)__cvta_generic_to_shared(p);
}
__device__ __forceinline__ void ldm_x4(uint32_t* r, uint32_t addr) {
    asm volatile("ldmatrix.sync.aligned.m8n8.x4.shared.b16 {%0,%1,%2,%3}, [%4];"
                 : "=r"(r[0]), "=r"(r[1]), "=r"(r[2]), "=r"(r[3]) : "r"(addr));
}
__device__ __forceinline__ void mma16816(float* c, const uint32_t* a,
                                         uint32_t b0, uint32_t b1) {
    asm volatile(
        "mma.sync.aligned.m16n8k16.row.col.f32.f16.f16.f32 "
        "{%0,%1,%2,%3}, {%4,%5,%6,%7}, {%8,%9}, {%0,%1,%2,%3};"
        : "+f"(c[0]), "+f"(c[1]), "+f"(c[2]), "+f"(c[3])
        : "r"(a[0]), "r"(a[1]), "r"(a[2]), "r"(a[3]), "r"(b0), "r"(b1));
}
__device__ __forceinline__ void cp16(uint32_t sm, const void* g) {
    asm volatile("cp.async.cg.shared.global [%0], [%1], 16;" :: "r"(sm), "l"(g));
}
__device__ __forceinline__ void cp_commit() {
    asm volatile("cp.async.commit_group;");
}
template <int N>
__device__ __forceinline__ void cp_wait() {
    asm volatile("cp.async.wait_group %0;" :: "n"(N));
}

// ============================================================
// 1) LayerNorm -> fp16
// ============================================================
__global__ __launch_bounds__(256) void ln_kernel(
    const float* __restrict__ x,
    const float* __restrict__ lnw, const float* __restrict__ lnb)
{
    int row  = blockIdx.x * 8 + (threadIdx.x >> 5);
    int lane = threadIdx.x & 31;
    int c0   = lane * 8;
    const float4* xr = reinterpret_cast<const float4*>(x + (size_t)row * C_ + c0);
    float4 f0 = xr[0], f1 = xr[1];
    float v[8] = {f0.x, f0.y, f0.z, f0.w, f1.x, f1.y, f1.z, f1.w};

    float s = 0.f, s2 = 0.f;
    #pragma unroll
    for (int j = 0; j < 8; j++) { s += v[j]; s2 += v[j] * v[j]; }
    #pragma unroll
    for (int o = 16; o > 0; o >>= 1) {
        s  += __shfl_xor_sync(0xffffffffu, s,  o);
        s2 += __shfl_xor_sync(0xffffffffu, s2, o);
    }
    float mu   = s * (1.0f / C_);
    float var  = s2 * (1.0f / C_) - mu * mu;
    float rstd = rsqrtf(var + 1e-5f);

    union { __half h[8]; uint4 u; } ha;
    #pragma unroll
    for (int j = 0; j < 8; j++) {
        float xn = (v[j] - mu) * rstd * lnw[c0 + j] + lnb[c0 + j];
        ha.h[j] = __float2half_rn(xn);
    }
    *reinterpret_cast<uint4*>(&g_xa[(size_t)row * C_ + c0]) = ha.u;
}

// ============================================================
// 2) Weight convert -> fp16, plus scan-flag reset
// ============================================================
__global__ __launch_bounds__(256) void wconv_kernel(
    const float* __restrict__ Wk, const float* __restrict__ Wv,
    const float* __restrict__ Wr, const float* __restrict__ Wo)
{
    int idx = blockIdx.x * 256 + threadIdx.x;
    if (idx < B_ * NC_) g_flag[idx] = 0;
    int mat = idx >> 16, rem = idx & 65535;
    float val = (mat == 0) ? Wk[rem] : (mat == 1) ? Wv[rem]
              : (mat == 2) ? Wr[rem] : Wo[rem];
    __half h = __float2half_rn(val);
    if (mat < 3) g_Wa[idx] = h;
    else         g_Woa[rem] = h;
}

// ============================================================
// 3) fp16 mma.sync GEMM, cp.async double-buffered.
//    outF != null -> fp32 out; else fp16 out at outH + z*MC_.
// ============================================================
__global__ void __launch_bounds__(256, 2) mma_gemm_kernel(
    const __half* __restrict__ A, const __half* __restrict__ W,
    float* __restrict__ outF, __half* __restrict__ outH,
    int nz, int sig_z)
{
    extern __shared__ __half sm[];
    uint32_t sbase = smem_u32(sm);

    int zc = blockIdx.x;
    int z  = zc % nz;
    int ny = zc / nz;
    size_t m0 = (size_t)blockIdx.y * BM;
    int n0 = ny * BN;
    const __half* w = W + (size_t)z * C_ * C_;

    int tid = threadIdx.x;
    int warp = tid >> 5, lane = tid & 31;
    int wm = (warp & 3) * 32;
    int wn = (warp >> 2) * 32;
    int gID = lane >> 2, tig = lane & 3;

    float acc[2][4][4];
    #pragma unroll
    for (int i = 0; i < 2; i++)
        #pragma unroll
        for (int j = 0; j < 4; j++)
            #pragma unroll
            for (int q = 0; q < 4; q++) acc[i][j][q] = 0.f;

    int arow  = lane & 15;
    int acolo = (lane >> 4) << 3;
    int q4 = lane >> 3;
    int brow_in = (lane & 7) + ((q4 >> 1) << 3);
    int bcolo = (q4 & 1) << 3;

    auto load_chunk = [&](int kc, int stg) {
        uint32_t base = sbase + stg * STAGE_B;
        int k0 = kc * KCH;
        #pragma unroll
        for (int it = 0; it < 4; it++) {
            int v = it * 256 + tid;
            int r = v >> 3, cv = v & 7;
            cp16(base + r * (SAS * 2) + cv * 16,
                 A + (m0 + r) * C_ + k0 + cv * 8);
        }
        #pragma unroll
        for (int it = 0; it < 2; it++) {
            int v = it * 256 + tid;
            int r = v >> 3, cv = v & 7;
            cp16(base + A_B + r * (SAS * 2) + cv * 16,
                 w + (size_t)(n0 + r) * C_ + k0 + cv * 8);
        }
        cp_commit();
    };

    load_chunk(0, 0);

    for (int kc = 0; kc < NKC; kc++) {
        cp_wait<0>();
        __syncthreads();
        if (kc + 1 < NKC) load_chunk(kc + 1, (kc + 1) & 1);

        uint32_t base = sbase + (kc & 1) * STAGE_B;
        uint32_t aB = base, bB = base + A_B;

        #pragma unroll
        for (int ks = 0; ks < KCH / 16; ks++) {
            int kk = ks * 16;
            uint32_t a[2][4], b[2][4];
            #pragma unroll
            for (int i = 0; i < 2; i++)
                ldm_x4(a[i], aB + (wm + i * 16 + arow) * (SAS * 2) + (kk + acolo) * 2);
            #pragma unroll
            for (int p = 0; p < 2; p++)
                ldm_x4(b[p], bB + (wn + p * 16 + brow_in) * (SAS * 2) + (kk + bcolo) * 2);
            #pragma unroll
            for (int i = 0; i < 2; i++)
                #pragma unroll
                for (int j = 0; j < 4; j++) {
                    int p = j >> 1, o = (j & 1) * 2;
                    mma16816(acc[i][j], a[i], b[p][o], b[p][o + 1]);
                }
        }
    }

    if (outF) {
        #pragma unroll
        for (int i = 0; i < 2; i++) {
            size_t row0 = m0 + wm + i * 16 + gID;
            #pragma unroll
            for (int j = 0; j < 4; j++) {
                int col = n0 + wn + j * 8 + tig * 2;
                *reinterpret_cast<float2*>(&outF[row0 * C_ + col]) =
                    make_float2(acc[i][j][0], acc[i][j][1]);
                *reinterpret_cast<float2*>(&outF[(row0 + 8) * C_ + col]) =
                    make_float2(acc[i][j][2], acc[i][j][3]);
            }
        }
    } else {
        bool sig = (z == sig_z);
        __half* oh = outH + (size_t)z * MC_;
        #pragma unroll
        for (int i = 0; i < 2; i++) {
            size_t row0 = m0 + wm + i * 16 + gID;
            #pragma unroll
            for (int j = 0; j < 4; j++) {
                int col = n0 + wn + j * 8 + tig * 2;
                float v0 = acc[i][j][0], v1 = acc[i][j][1];
                float v2 = acc[i][j][2], v3 = acc[i][j][3];
                if (sig) {
                    v0 = 1.0f / (1.0f + __expf(-v0));
                    v1 = 1.0f / (1.0f + __expf(-v1));
                    v2 = 1.0f / (1.0f + __expf(-v2));
                    v3 = 1.0f / (1.0f + __expf(-v3));
                }
                *reinterpret_cast<__half2*>(&oh[row0 * C_ + col]) =
                    __floats2half2_rn(v0, v1);
                *reinterpret_cast<__half2*>(&oh[(row0 + 8) * C_ + col]) =
                    __floats2half2_rn(v2, v3);
            }
        }
    }
}

// ============================================================
// 4) Fused scan: local scan + chained carry + y = r*(s+v).
//    grid (NC_, B_), 64 threads (4 channels each, half2 x2 loads).
//    Deterministic: strict wait on predecessor's inclusive state.
// ============================================================
__global__ void __launch_bounds__(64) scan_fused_kernel(const float* __restrict__ td) {
    int j = blockIdx.x, b = blockIdx.y;
    int t = threadIdx.x;
    int c0 = t * 4;

    float4 tdv = *reinterpret_cast<const float4*>(td + c0);
    float rx = fmaxf(tdv.x, 0.f), ry = fmaxf(tdv.y, 0.f);
    float rz = fmaxf(tdv.z, 0.f), rw = fmaxf(tdv.w, 0.f);
    float dx = expf(-rx), dy = expf(-ry), dz = expf(-rz), dw = expf(-rw);
    float dLx = expf(-rx * (float)L_), dLy = expf(-ry * (float)L_);
    float dLz = expf(-rz * (float)L_), dLw = expf(-rw * (float)L_);

    size_t base = ((size_t)(b * N_ + j * L_)) * C_ + c0;
    const __half* kp = g_kvr;

    // ---- pass 1: local aggregate (carry-free scan) ----
    float4 s = make_float4(0.f, 0.f, 0.f, 0.f);
    #pragma unroll 8
    for (int i = 0; i < L_; i++) {
        uint2 raw = *reinterpret_cast<const uint2*>(&kp[base + (size_t)i * C_]);
        __half2 k01 = *reinterpret_cast<__half2*>(&raw.x);
        __half2 k23 = *reinterpret_cast<__half2*>(&raw.y);
        s.x = fmaf(s.x, dx, __low2float(k01));
        s.y = fmaf(s.y, dy, __high2float(k01));
        s.z = fmaf(s.z, dz, __low2float(k23));
        s.w = fmaf(s.w, dw, __high2float(k23));
    }

    // ---- carry chain ----
    int idx = b * NC_ + j;
    float4 carry = make_float4(0.f, 0.f, 0.f, 0.f);
    if (j > 0) {
        if (t == 0) {
            volatile int* fl = g_flag;
            while (fl[idx - 1] == 0) {}
        }
        __syncthreads();
        __threadfence();
        const float* ip = g_incl + (size_t)(idx - 1) * C_ + c0;
        carry.x = __ldcg(ip + 0); carry.y = __ldcg(ip + 1);
        carry.z = __ldcg(ip + 2); carry.w = __ldcg(ip + 3);
    }
    if (j < NC_ - 1) {
        float* op = g_incl + (size_t)idx * C_ + c0;
        op[0] = fmaf(dLx, carry.x, s.x);
        op[1] = fmaf(dLy, carry.y, s.y);
        op[2] = fmaf(dLz, carry.z, s.z);
        op[3] = fmaf(dLw, carry.w, s.w);
        __threadfence();
        __syncthreads();
        if (t == 0) atomicExch(&g_flag[idx], 1);
    }

    // ---- pass 2: full scan with carry, fused output ----
    s = carry;
    #pragma unroll 4
    for (int i = 0; i < L_; i++) {
        size_t off = base + (size_t)i * C_;
        uint2 kraw = *reinterpret_cast<const uint2*>(&kp[off]);
        uint2 vraw = *reinterpret_cast<const uint2*>(&kp[MC_ + off]);
        uint2 rraw = *reinterpret_cast<const uint2*>(&kp[2 * MC_ + off]);
        __half2 k01 = *reinterpret_cast<__half2*>(&kraw.x);
        __half2 k23 = *reinterpret_cast<__half2*>(&kraw.y);
        __half2 v01 = *reinterpret_cast<__half2*>(&vraw.x);
        __half2 v23 = *reinterpret_cast<__half2*>(&vraw.y);
        __half2 r01 = *reinterpret_cast<__half2*>(&rraw.x);
        __half2 r23 = *reinterpret_cast<__half2*>(&rraw.y);
        s.x = fmaf(s.x, dx, __low2float(k01));
        s.y = fmaf(s.y, dy, __high2float(k01));
        s.z = fmaf(s.z, dz, __low2float(k23));
        s.w = fmaf(s.w, dw, __high2float(k23));
        float y0 = __low2float(r01)  * (s.x + __low2float(v01));
        float y1 = __high2float(r01) * (s.y + __high2float(v01));
        float y2 = __low2float(r23)  * (s.z + __low2float(v23));
        float y3 = __high2float(r23) * (s.w + __high2float(v23));
        union { __half2 h2[2]; uint2 u; } Y;
        Y.h2[0] = __floats2half2_rn(y0, y1);
        Y.h2[1] = __floats2half2_rn(y2, y3);
        *reinterpret_cast<uint2*>(&g_ya[off]) = Y.u;
    }
}

// ============================================================
// launch
// ============================================================
extern "C" void kernel_launch(void* const* d_in, const int* in_sizes, int n_in,
                              void* d_out, int out_size) {
    const float* x   = (const float*)d_in[0];
    const float* td  = (const float*)d_in[1];
    const float* Wk  = (const float*)d_in[2];
    const float* Wv  = (const float*)d_in[3];
    const float* Wr  = (const float*)d_in[4];
    const float* Wo  = (const float*)d_in[5];
    const float* lnw = (const float*)d_in[6];
    const float* lnb = (const float*)d_in[7];
    float* out = (float*)d_out;

    __half *xa, *ya, *Wa, *Woa, *kvr;
    cudaGetSymbolAddress((void**)&xa,  g_xa);
    cudaGetSymbolAddress((void**)&ya,  g_ya);
    cudaGetSymbolAddress((void**)&Wa,  g_Wa);
    cudaGetSymbolAddress((void**)&Woa, g_Woa);
    cudaGetSymbolAddress((void**)&kvr, g_kvr);

    cudaFuncSetAttribute(mma_gemm_kernel,
                         cudaFuncAttributeMaxDynamicSharedMemorySize, SMEM_REQ);

    ln_kernel<<<M_ / 8, 256>>>(x, lnw, lnb);
    wconv_kernel<<<1024, 256>>>(Wk, Wv, Wr, Wo);
    // z=0 -> k, z=1 -> v, z=2 -> sigmoid(r); all fp16
    mma_gemm_kernel<<<dim3((C_ / BN) * 3, M_ / BM), 256, SMEM_REQ>>>(
        xa, Wa, nullptr, kvr, 3, 2);
    scan_fused_kernel<<<dim3(NC_, B_), 64>>>(td);
    // output GEMM -> fp32
    mma_gemm_kernel<<<dim3(C_ / BN, M_ / BM), 256, SMEM_REQ>>>(
        ya, Woa, out, nullptr, 1, -1);
}

// round 8
// speedup vs baseline: 1.3265x; 1.3265x over previous
#include <cuda_runtime.h>
#include <cuda_fp16.h>
#include <math.h>
#include <stdint.h>

#define B_  8
#define N_  16384
#define C_  256
#define M_  (B_*N_)      // 131072 rows
#define MC_ ((size_t)M_*C_)
#define L_  128          // scan chunk length
#define NC_ (N_/L_)      // 128 chunks per batch

// ---- GEMM tiling ----
#define BM 128
#define BN 64
#define KCH 64
#define NKC (C_/KCH)           // 4
#define SAS 72                 // smem row stride in halves (144B)
#define A_B (BM*SAS*2)
#define B_B (BN*SAS*2)
#define STAGE_B (A_B + B_B)
#define SMEM_REQ (2*STAGE_B)   // 55296

// ---- scratch ----
__device__ __half g_kvr[3*MC_];        // k, v, r  (fp16)
__device__ __half g_xa[MC_];           // LN(x) fp16
__device__ __half g_ya[MC_];           // y fp16
__device__ __half g_Wa[3*C_*C_];       // Wk,Wv,Wr fp16
__device__ __half g_Woa[C_*C_];        // Wo fp16
__device__ float  g_e[B_*NC_*C_];      // chunk-local end states
__device__ float  g_carry[B_*NC_*C_];  // injected carries

// ============================================================
// helpers
// ============================================================
__device__ __forceinline__ uint32_t smem_u32(const void* p) {
    return (uint32_t)__cvta_generic_to_shared(p);
}
__device__ __forceinline__ void ldm_x4(uint32_t* r, uint32_t addr) {
    asm volatile("ldmatrix.sync.aligned.m8n8.x4.shared.b16 {%0,%1,%2,%3}, [%4];"
                 : "=r"(r[0]), "=r"(r[1]), "=r"(r[2]), "=r"(r[3]) : "r"(addr));
}
__device__ __forceinline__ void mma16816(float* c, const uint32_t* a,
                                         uint32_t b0, uint32_t b1) {
    asm volatile(
        "mma.sync.aligned.m16n8k16.row.col.f32.f16.f16.f32 "
        "{%0,%1,%2,%3}, {%4,%5,%6,%7}, {%8,%9}, {%0,%1,%2,%3};"
        : "+f"(c[0]), "+f"(c[1]), "+f"(c[2]), "+f"(c[3])
        : "r"(a[0]), "r"(a[1]), "r"(a[2]), "r"(a[3]), "r"(b0), "r"(b1));
}
__device__ __forceinline__ void cp16(uint32_t sm, const void* g) {
    asm volatile("cp.async.cg.shared.global [%0], [%1], 16;" :: "r"(sm), "l"(g));
}
__device__ __forceinline__ void cp_commit() {
    asm volatile("cp.async.commit_group;");
}
template <int N>
__device__ __forceinline__ void cp_wait() {
    asm volatile("cp.async.wait_group %0;" :: "n"(N));
}

// ============================================================
// 1) LayerNorm -> fp16
// ============================================================
__global__ __launch_bounds__(256) void ln_kernel(
    const float* __restrict__ x,
    const float* __restrict__ lnw, const float* __restrict__ lnb)
{
    int row  = blockIdx.x * 8 + (threadIdx.x >> 5);
    int lane = threadIdx.x & 31;
    int c0   = lane * 8;
    const float4* xr = reinterpret_cast<const float4*>(x + (size_t)row * C_ + c0);
    float4 f0 = xr[0], f1 = xr[1];
    float v[8] = {f0.x, f0.y, f0.z, f0.w, f1.x, f1.y, f1.z, f1.w};

    float s = 0.f, s2 = 0.f;
    #pragma unroll
    for (int j = 0; j < 8; j++) { s += v[j]; s2 += v[j] * v[j]; }
    #pragma unroll
    for (int o = 16; o > 0; o >>= 1) {
        s  += __shfl_xor_sync(0xffffffffu, s,  o);
        s2 += __shfl_xor_sync(0xffffffffu, s2, o);
    }
    float mu   = s * (1.0f / C_);
    float var  = s2 * (1.0f / C_) - mu * mu;
    float rstd = rsqrtf(var + 1e-5f);

    union { __half h[8]; uint4 u; } ha;
    #pragma unroll
    for (int j = 0; j < 8; j++) {
        float xn = (v[j] - mu) * rstd * lnw[c0 + j] + lnb[c0 + j];
        ha.h[j] = __float2half_rn(xn);
    }
    *reinterpret_cast<uint4*>(&g_xa[(size_t)row * C_ + c0]) = ha.u;
}

// ============================================================
// 2) Weight convert -> fp16
// ============================================================
__global__ __launch_bounds__(256) void wconv_kernel(
    const float* __restrict__ Wk, const float* __restrict__ Wv,
    const float* __restrict__ Wr, const float* __restrict__ Wo)
{
    int idx = blockIdx.x * 256 + threadIdx.x;
    int mat = idx >> 16, rem = idx & 65535;
    float val = (mat == 0) ? Wk[rem] : (mat == 1) ? Wv[rem]
              : (mat == 2) ? Wr[rem] : Wo[rem];
    __half h = __float2half_rn(val);
    if (mat < 3) g_Wa[idx] = h;
    else         g_Woa[rem] = h;
}

// ============================================================
// 3) fp16 mma.sync GEMM, cp.async double-buffered.
//    outF != null -> fp32 out; else fp16 out at outH + z*MC_.
// ============================================================
__global__ void __launch_bounds__(256, 2) mma_gemm_kernel(
    const __half* __restrict__ A, const __half* __restrict__ W,
    float* __restrict__ outF, __half* __restrict__ outH,
    int nz, int sig_z)
{
    extern __shared__ __half sm[];
    uint32_t sbase = smem_u32(sm);

    int zc = blockIdx.x;
    int z  = zc % nz;
    int ny = zc / nz;
    size_t m0 = (size_t)blockIdx.y * BM;
    int n0 = ny * BN;
    const __half* w = W + (size_t)z * C_ * C_;

    int tid = threadIdx.x;
    int warp = tid >> 5, lane = tid & 31;
    int wm = (warp & 3) * 32;
    int wn = (warp >> 2) * 32;
    int gID = lane >> 2, tig = lane & 3;

    float acc[2][4][4];
    #pragma unroll
    for (int i = 0; i < 2; i++)
        #pragma unroll
        for (int j = 0; j < 4; j++)
            #pragma unroll
            for (int q = 0; q < 4; q++) acc[i][j][q] = 0.f;

    int arow  = lane & 15;
    int acolo = (lane >> 4) << 3;
    int q4 = lane >> 3;
    int brow_in = (lane & 7) + ((q4 >> 1) << 3);
    int bcolo = (q4 & 1) << 3;

    auto load_chunk = [&](int kc, int stg) {
        uint32_t base = sbase + stg * STAGE_B;
        int k0 = kc * KCH;
        #pragma unroll
        for (int it = 0; it < 4; it++) {
            int v = it * 256 + tid;
            int r = v >> 3, cv = v & 7;
            cp16(base + r * (SAS * 2) + cv * 16,
                 A + (m0 + r) * C_ + k0 + cv * 8);
        }
        #pragma unroll
        for (int it = 0; it < 2; it++) {
            int v = it * 256 + tid;
            int r = v >> 3, cv = v & 7;
            cp16(base + A_B + r * (SAS * 2) + cv * 16,
                 w + (size_t)(n0 + r) * C_ + k0 + cv * 8);
        }
        cp_commit();
    };

    load_chunk(0, 0);

    for (int kc = 0; kc < NKC; kc++) {
        cp_wait<0>();
        __syncthreads();
        if (kc + 1 < NKC) load_chunk(kc + 1, (kc + 1) & 1);

        uint32_t base = sbase + (kc & 1) * STAGE_B;
        uint32_t aB = base, bB = base + A_B;

        #pragma unroll
        for (int ks = 0; ks < KCH / 16; ks++) {
            int kk = ks * 16;
            uint32_t a[2][4], b[2][4];
            #pragma unroll
            for (int i = 0; i < 2; i++)
                ldm_x4(a[i], aB + (wm + i * 16 + arow) * (SAS * 2) + (kk + acolo) * 2);
            #pragma unroll
            for (int p = 0; p < 2; p++)
                ldm_x4(b[p], bB + (wn + p * 16 + brow_in) * (SAS * 2) + (kk + bcolo) * 2);
            #pragma unroll
            for (int i = 0; i < 2; i++)
                #pragma unroll
                for (int j = 0; j < 4; j++) {
                    int p = j >> 1, o = (j & 1) * 2;
                    mma16816(acc[i][j], a[i], b[p][o], b[p][o + 1]);
                }
        }
    }

    if (outF) {
        #pragma unroll
        for (int i = 0; i < 2; i++) {
            size_t row0 = m0 + wm + i * 16 + gID;
            #pragma unroll
            for (int j = 0; j < 4; j++) {
                int col = n0 + wn + j * 8 + tig * 2;
                *reinterpret_cast<float2*>(&outF[row0 * C_ + col]) =
                    make_float2(acc[i][j][0], acc[i][j][1]);
                *reinterpret_cast<float2*>(&outF[(row0 + 8) * C_ + col]) =
                    make_float2(acc[i][j][2], acc[i][j][3]);
            }
        }
    } else {
        bool sig = (z == sig_z);
        __half* oh = outH + (size_t)z * MC_;
        #pragma unroll
        for (int i = 0; i < 2; i++) {
            size_t row0 = m0 + wm + i * 16 + gID;
            #pragma unroll
            for (int j = 0; j < 4; j++) {
                int col = n0 + wn + j * 8 + tig * 2;
                float v0 = acc[i][j][0], v1 = acc[i][j][1];
                float v2 = acc[i][j][2], v3 = acc[i][j][3];
                if (sig) {
                    v0 = 1.0f / (1.0f + __expf(-v0));
                    v1 = 1.0f / (1.0f + __expf(-v1));
                    v2 = 1.0f / (1.0f + __expf(-v2));
                    v3 = 1.0f / (1.0f + __expf(-v3));
                }
                *reinterpret_cast<__half2*>(&oh[row0 * C_ + col]) =
                    __floats2half2_rn(v0, v1);
                *reinterpret_cast<__half2*>(&oh[(row0 + 8) * C_ + col]) =
                    __floats2half2_rn(v2, v3);
            }
        }
    }
}

// ============================================================
// 4) Scan pass 1: local chunk scans (fp16 k), end values only.
//    grid (NC_/4, B_), block 256: 64 threads x 4ch per chunk.
// ============================================================
__global__ __launch_bounds__(256) void scan1_kernel(const float* __restrict__ td) {
    int sub = threadIdx.x >> 6, t = threadIdx.x & 63;
    int j = blockIdx.x * 4 + sub, b = blockIdx.y;
    int c0 = t * 4;
    float4 tdv = *reinterpret_cast<const float4*>(td + c0);
    float dx = expf(-fmaxf(tdv.x, 0.f)), dy = expf(-fmaxf(tdv.y, 0.f));
    float dz = expf(-fmaxf(tdv.z, 0.f)), dw = expf(-fmaxf(tdv.w, 0.f));
    size_t base = ((size_t)(b * N_ + j * L_)) * C_ + c0;
    float4 s = make_float4(0.f, 0.f, 0.f, 0.f);
    #pragma unroll 8
    for (int i = 0; i < L_; i++) {
        uint2 raw = *reinterpret_cast<const uint2*>(&g_kvr[base + (size_t)i * C_]);
        __half2 k01 = *reinterpret_cast<__half2*>(&raw.x);
        __half2 k23 = *reinterpret_cast<__half2*>(&raw.y);
        s.x = fmaf(s.x, dx, __low2float(k01));
        s.y = fmaf(s.y, dy, __high2float(k01));
        s.z = fmaf(s.z, dz, __low2float(k23));
        s.w = fmaf(s.w, dw, __high2float(k23));
    }
    reinterpret_cast<float4*>(g_e + (size_t)(b * NC_ + j) * C_)[t] = s;
}

// ============================================================
// 5) Carry propagation, batched independent loads
// ============================================================
__global__ __launch_bounds__(256) void scan_carry_kernel(const float* __restrict__ td) {
    int b = blockIdx.x, c = threadIdx.x;
    float r  = fmaxf(td[c], 0.f);
    float dL = expf(-r * (float)L_);
    float cy = 0.f;
    for (int jb = 0; jb < NC_; jb += 8) {
        float e[8];
        #pragma unroll
        for (int u = 0; u < 8; u++) e[u] = g_e[(size_t)(b * NC_ + jb + u) * C_ + c];
        #pragma unroll
        for (int u = 0; u < 8; u++) {
            g_carry[(size_t)(b * NC_ + jb + u) * C_ + c] = cy;
            cy = fmaf(dL, cy, e[u]);
        }
    }
}

// ============================================================
// 6) Scan pass 2 + y = r*(s+v) -> fp16.  grid (NC_/4, B_)
// ============================================================
__global__ __launch_bounds__(256) void scan2_kernel(const float* __restrict__ td) {
    int sub = threadIdx.x >> 6, t = threadIdx.x & 63;
    int j = blockIdx.x * 4 + sub, b = blockIdx.y;
    int c0 = t * 4;
    float4 tdv = *reinterpret_cast<const float4*>(td + c0);
    float dx = expf(-fmaxf(tdv.x, 0.f)), dy = expf(-fmaxf(tdv.y, 0.f));
    float dz = expf(-fmaxf(tdv.z, 0.f)), dw = expf(-fmaxf(tdv.w, 0.f));
    size_t base = ((size_t)(b * N_ + j * L_)) * C_ + c0;
    float4 s = reinterpret_cast<const float4*>(g_carry + (size_t)(b * NC_ + j) * C_)[t];
    #pragma unroll 4
    for (int i = 0; i < L_; i++) {
        size_t off = base + (size_t)i * C_;
        uint2 kraw = *reinterpret_cast<const uint2*>(&g_kvr[off]);
        uint2 vraw = *reinterpret_cast<const uint2*>(&g_kvr[MC_ + off]);
        uint2 rraw = *reinterpret_cast<const uint2*>(&g_kvr[2 * MC_ + off]);
        __half2 k01 = *reinterpret_cast<__half2*>(&kraw.x);
        __half2 k23 = *reinterpret_cast<__half2*>(&kraw.y);
        __half2 v01 = *reinterpret_cast<__half2*>(&vraw.x);
        __half2 v23 = *reinterpret_cast<__half2*>(&vraw.y);
        __half2 r01 = *reinterpret_cast<__half2*>(&rraw.x);
        __half2 r23 = *reinterpret_cast<__half2*>(&rraw.y);
        s.x = fmaf(s.x, dx, __low2float(k01));
        s.y = fmaf(s.y, dy, __high2float(k01));
        s.z = fmaf(s.z, dz, __low2float(k23));
        s.w = fmaf(s.w, dw, __high2float(k23));
        float y0 = __low2float(r01)  * (s.x + __low2float(v01));
        float y1 = __high2float(r01) * (s.y + __high2float(v01));
        float y2 = __low2float(r23)  * (s.z + __low2float(v23));
        float y3 = __high2float(r23) * (s.w + __high2float(v23));
        union { __half2 h2[2]; uint2 u; } Y;
        Y.h2[0] = __floats2half2_rn(y0, y1);
        Y.h2[1] = __floats2half2_rn(y2, y3);
        *reinterpret_cast<uint2*>(&g_ya[off]) = Y.u;
    }
}

// ============================================================
// launch
// ============================================================
extern "C" void kernel_launch(void* const* d_in, const int* in_sizes, int n_in,
                              void* d_out, int out_size) {
    const float* x   = (const float*)d_in[0];
    const float* td  = (const float*)d_in[1];
    const float* Wk  = (const float*)d_in[2];
    const float* Wv  = (const float*)d_in[3];
    const float* Wr  = (const float*)d_in[4];
    const float* Wo  = (const float*)d_in[5];
    const float* lnw = (const float*)d_in[6];
    const float* lnb = (const float*)d_in[7];
    float* out = (float*)d_out;

    __half *xa, *ya, *Wa, *Woa, *kvr;
    cudaGetSymbolAddress((void**)&xa,  g_xa);
    cudaGetSymbolAddress((void**)&ya,  g_ya);
    cudaGetSymbolAddress((void**)&Wa,  g_Wa);
    cudaGetSymbolAddress((void**)&Woa, g_Woa);
    cudaGetSymbolAddress((void**)&kvr, g_kvr);

    cudaFuncSetAttribute(mma_gemm_kernel,
                         cudaFuncAttributeMaxDynamicSharedMemorySize, SMEM_REQ);

    ln_kernel<<<M_ / 8, 256>>>(x, lnw, lnb);
    wconv_kernel<<<1024, 256>>>(Wk, Wv, Wr, Wo);
    // z=0 -> k, z=1 -> v, z=2 -> sigmoid(r); all fp16
    mma_gemm_kernel<<<dim3((C_ / BN) * 3, M_ / BM), 256, SMEM_REQ>>>(
        xa, Wa, nullptr, kvr, 3, 2);
    scan1_kernel<<<dim3(NC_ / 4, B_), 256>>>(td);
    scan_carry_kernel<<<B_, 256>>>(td);
    scan2_kernel<<<dim3(NC_ / 4, B_), 256>>>(td);
    // output GEMM -> fp32
    mma_gemm_kernel<<<dim3(C_ / BN, M_ / BM), 256, SMEM_REQ>>>(
        ya, Woa, out, nullptr, 1, -1);
}

// round 11
// speedup vs baseline: 1.4673x; 1.1062x over previous
#include <cuda_runtime.h>
#include <cuda_fp16.h>
#include <math.h>
#include <stdint.h>

#define B_  8
#define N_  16384
#define C_  256
#define M_  (B_*N_)      // 131072 rows
#define MC_ ((size_t)M_*C_)
#define L_  128          // scan chunk length
#define NC_ (N_/L_)      // 128 chunks per batch

// ---- GEMM tiling ----
#define BM 128
#define BN 128
#define KCH 64
#define NKC (C_/KCH)           // 4
#define SAS 72                 // smem row stride in halves (144B)
#define A_B (BM*SAS*2)         // 18432
#define B_B (BN*SAS*2)         // 18432
#define STAGE_B (A_B + B_B)    // 36864
#define SMEM_REQ (2*STAGE_B)   // 73728
#define SDS 136                // fp16 staging stride (halves; 272B, 16B-aligned rows)
#define SDF 132                // fp32 staging stride (floats; 528B, 16B-aligned rows)

// ---- scratch ----
__device__ __half g_kvr[3*MC_];        // k, v, r  (fp16)
__device__ __half g_xa[MC_];           // LN(x) fp16
__device__ __half g_ya[MC_];           // y fp16
__device__ __half g_Wa[3*C_*C_];       // Wk,Wv,Wr fp16
__device__ __half g_Woa[C_*C_];        // Wo fp16
__device__ float  g_e[B_*NC_*C_];      // chunk-local end states
__device__ float  g_carry[B_*NC_*C_];  // injected carries

// ============================================================
// helpers
// ============================================================
__device__ __forceinline__ uint32_t smem_u32(const void* p) {
    return (uint32_t)__cvta_generic_to_shared(p);
}
__device__ __forceinline__ void ldm_x4(uint32_t* r, uint32_t addr) {
    asm volatile("ldmatrix.sync.aligned.m8n8.x4.shared.b16 {%0,%1,%2,%3}, [%4];"
                 : "=r"(r[0]), "=r"(r[1]), "=r"(r[2]), "=r"(r[3]) : "r"(addr));
}
__device__ __forceinline__ void mma16816(float* c, const uint32_t* a,
                                         uint32_t b0, uint32_t b1) {
    asm volatile(
        "mma.sync.aligned.m16n8k16.row.col.f32.f16.f16.f32 "
        "{%0,%1,%2,%3}, {%4,%5,%6,%7}, {%8,%9}, {%0,%1,%2,%3};"
        : "+f"(c[0]), "+f"(c[1]), "+f"(c[2]), "+f"(c[3])
        : "r"(a[0]), "r"(a[1]), "r"(a[2]), "r"(a[3]), "r"(b0), "r"(b1));
}
__device__ __forceinline__ void cp16(uint32_t sm, const void* g) {
    asm volatile("cp.async.cg.shared.global [%0], [%1], 16;" :: "r"(sm), "l"(g));
}
__device__ __forceinline__ void cp_commit() {
    asm volatile("cp.async.commit_group;");
}
template <int N>
__device__ __forceinline__ void cp_wait() {
    asm volatile("cp.async.wait_group %0;" :: "n"(N));
}

// ============================================================
// 1) LayerNorm -> fp16
// ============================================================
__global__ __launch_bounds__(256) void ln_kernel(
    const float* __restrict__ x,
    const float* __restrict__ lnw, const float* __restrict__ lnb)
{
    int row  = blockIdx.x * 8 + (threadIdx.x >> 5);
    int lane = threadIdx.x & 31;
    int c0   = lane * 8;
    const float4* xr = reinterpret_cast<const float4*>(x + (size_t)row * C_ + c0);
    float4 f0 = xr[0], f1 = xr[1];
    float v[8] = {f0.x, f0.y, f0.z, f0.w, f1.x, f1.y, f1.z, f1.w};

    float s = 0.f, s2 = 0.f;
    #pragma unroll
    for (int j = 0; j < 8; j++) { s += v[j]; s2 += v[j] * v[j]; }
    #pragma unroll
    for (int o = 16; o > 0; o >>= 1) {
        s  += __shfl_xor_sync(0xffffffffu, s,  o);
        s2 += __shfl_xor_sync(0xffffffffu, s2, o);
    }
    float mu   = s * (1.0f / C_);
    float var  = s2 * (1.0f / C_) - mu * mu;
    float rstd = rsqrtf(var + 1e-5f);

    union { __half h[8]; uint4 u; } ha;
    #pragma unroll
    for (int j = 0; j < 8; j++) {
        float xn = (v[j] - mu) * rstd * lnw[c0 + j] + lnb[c0 + j];
        ha.h[j] = __float2half_rn(xn);
    }
    *reinterpret_cast<uint4*>(&g_xa[(size_t)row * C_ + c0]) = ha.u;
}

// ============================================================
// 2) Weight convert -> fp16
// ============================================================
__global__ __launch_bounds__(256) void wconv_kernel(
    const float* __restrict__ Wk, const float* __restrict__ Wv,
    const float* __restrict__ Wr, const float* __restrict__ Wo)
{
    int idx = blockIdx.x * 256 + threadIdx.x;
    int mat = idx >> 16, rem = idx & 65535;
    float val = (mat == 0) ? Wk[rem] : (mat == 1) ? Wv[rem]
              : (mat == 2) ? Wr[rem] : Wo[rem];
    __half h = __float2half_rn(val);
    if (mat < 3) g_Wa[idx] = h;
    else         g_Woa[rem] = h;
}

// ============================================================
// 3) fp16 mma.sync GEMM.  Block 128x128, warp tile 32x64,
//    cp.async double-buffered over K=256.  Coalesced smem-staged
//    epilogue.  outF != null -> fp32 out; else fp16 at outH+z*MC_.
// ============================================================
__global__ void __launch_bounds__(256, 2) mma_gemm_kernel(
    const __half* __restrict__ A, const __half* __restrict__ W,
    float* __restrict__ outF, __half* __restrict__ outH,
    int nz, int sig_z)
{
    extern __shared__ __half sm[];
    uint32_t sbase = smem_u32(sm);

    int zc = blockIdx.x;
    int z  = zc % nz;
    int ny = zc / nz;
    size_t m0 = (size_t)blockIdx.y * BM;
    int n0 = ny * BN;
    const __half* w = W + (size_t)z * C_ * C_;

    int tid = threadIdx.x;
    int warp = tid >> 5, lane = tid & 31;
    int wm = (warp & 3) * 32;          // 4 m-warps
    int wn = (warp >> 2) * 64;         // 2 n-warps
    int gID = lane >> 2, tig = lane & 3;

    float acc[2][8][4];
    #pragma unroll
    for (int i = 0; i < 2; i++)
        #pragma unroll
        for (int j = 0; j < 8; j++)
            #pragma unroll
            for (int q = 0; q < 4; q++) acc[i][j][q] = 0.f;

    int arow  = lane & 15;
    int acolo = (lane >> 4) << 3;
    int q4 = lane >> 3;
    int brow_in = (lane & 7) + ((q4 >> 1) << 3);
    int bcolo = (q4 & 1) << 3;

    auto load_chunk = [&](int kc, int stg) {
        uint32_t base = sbase + stg * STAGE_B;
        int k0 = kc * KCH;
        #pragma unroll
        for (int it = 0; it < 4; it++) {          // A: 1024 vec16
            int v = it * 256 + tid;
            int r = v >> 3, cv = v & 7;
            cp16(base + r * (SAS * 2) + cv * 16,
                 A + (m0 + r) * C_ + k0 + cv * 8);
        }
        #pragma unroll
        for (int it = 0; it < 4; it++) {          // B: 1024 vec16
            int v = it * 256 + tid;
            int r = v >> 3, cv = v & 7;
            cp16(base + A_B + r * (SAS * 2) + cv * 16,
                 w + (size_t)(n0 + r) * C_ + k0 + cv * 8);
        }
        cp_commit();
    };

    load_chunk(0, 0);

    for (int kc = 0; kc < NKC; kc++) {
        cp_wait<0>();
        __syncthreads();
        if (kc + 1 < NKC) load_chunk(kc + 1, (kc + 1) & 1);

        uint32_t base = sbase + (kc & 1) * STAGE_B;
        uint32_t aB = base, bB = base + A_B;

        #pragma unroll
        for (int ks = 0; ks < KCH / 16; ks++) {
            int kk = ks * 16;
            uint32_t a[2][4], b[4][4];
            #pragma unroll
            for (int i = 0; i < 2; i++)
                ldm_x4(a[i], aB + (wm + i * 16 + arow) * (SAS * 2) + (kk + acolo) * 2);
            #pragma unroll
            for (int p = 0; p < 4; p++)
                ldm_x4(b[p], bB + (wn + p * 16 + brow_in) * (SAS * 2) + (kk + bcolo) * 2);
            #pragma unroll
            for (int i = 0; i < 2; i++)
                #pragma unroll
                for (int j = 0; j < 8; j++) {
                    int p = j >> 1, o = (j & 1) * 2;
                    mma16816(acc[i][j], a[i], b[p][o], b[p][o + 1]);
                }
        }
    }
    __syncthreads();   // done with stage buffers; reuse as staging

    if (outF) {
        // ---- fp32 staging + coalesced copy ----
        float* sD = reinterpret_cast<float*>(sm);
        #pragma unroll
        for (int i = 0; i < 2; i++) {
            int row = wm + i * 16 + gID;
            #pragma unroll
            for (int j = 0; j < 8; j++) {
                int col = wn + j * 8 + tig * 2;
                *reinterpret_cast<float2*>(&sD[row * SDF + col]) =
                    make_float2(acc[i][j][0], acc[i][j][1]);
                *reinterpret_cast<float2*>(&sD[(row + 8) * SDF + col]) =
                    make_float2(acc[i][j][2], acc[i][j][3]);
            }
        }
        __syncthreads();
        #pragma unroll
        for (int it = 0; it < 16; it++) {         // 128 rows x 32 seg16B
            int idx = it * 256 + tid;
            int row = idx >> 5, seg = idx & 31;
            float4 v = *reinterpret_cast<float4*>(&sD[row * SDF + seg * 4]);
            *reinterpret_cast<float4*>(&outF[(m0 + row) * C_ + n0 + seg * 4]) = v;
        }
    } else {
        // ---- fp16 staging + coalesced copy ----
        bool sig = (z == sig_z);
        __half* sD = sm;
        #pragma unroll
        for (int i = 0; i < 2; i++) {
            int row = wm + i * 16 + gID;
            #pragma unroll
            for (int j = 0; j < 8; j++) {
                int col = wn + j * 8 + tig * 2;
                float v0 = acc[i][j][0], v1 = acc[i][j][1];
                float v2 = acc[i][j][2], v3 = acc[i][j][3];
                if (sig) {
                    v0 = 1.0f / (1.0f + __expf(-v0));
                    v1 = 1.0f / (1.0f + __expf(-v1));
                    v2 = 1.0f / (1.0f + __expf(-v2));
                    v3 = 1.0f / (1.0f + __expf(-v3));
                }
                *reinterpret_cast<__half2*>(&sD[row * SDS + col]) =
                    __floats2half2_rn(v0, v1);
                *reinterpret_cast<__half2*>(&sD[(row + 8) * SDS + col]) =
                    __floats2half2_rn(v2, v3);
            }
        }
        __syncthreads();
        __half* oh = outH + (size_t)z * MC_;
        #pragma unroll
        for (int it = 0; it < 8; it++) {          // 128 rows x 16 seg16B
            int idx = it * 256 + tid;
            int row = idx >> 4, seg = idx & 15;
            uint4 v = *reinterpret_cast<uint4*>(&sD[row * SDS + seg * 8]);
            *reinterpret_cast<uint4*>(&oh[(m0 + row) * C_ + n0 + seg * 8]) = v;
        }
    }
}

// ============================================================
// 4) Scan pass 1: local chunk scans (fp16 k), end values only.
// ============================================================
__global__ __launch_bounds__(256) void scan1_kernel(const float* __restrict__ td) {
    int sub = threadIdx.x >> 6, t = threadIdx.x & 63;
    int j = blockIdx.x * 4 + sub, b = blockIdx.y;
    int c0 = t * 4;
    float4 tdv = *reinterpret_cast<const float4*>(td + c0);
    float dx = expf(-fmaxf(tdv.x, 0.f)), dy = expf(-fmaxf(tdv.y, 0.f));
    float dz = expf(-fmaxf(tdv.z, 0.f)), dw = expf(-fmaxf(tdv.w, 0.f));
    size_t base = ((size_t)(b * N_ + j * L_)) * C_ + c0;
    float4 s = make_float4(0.f, 0.f, 0.f, 0.f);
    #pragma unroll 8
    for (int i = 0; i < L_; i++) {
        uint2 raw = *reinterpret_cast<const uint2*>(&g_kvr[base + (size_t)i * C_]);
        __half2 k01 = *reinterpret_cast<__half2*>(&raw.x);
        __half2 k23 = *reinterpret_cast<__half2*>(&raw.y);
        s.x = fmaf(s.x, dx, __low2float(k01));
        s.y = fmaf(s.y, dy, __high2float(k01));
        s.z = fmaf(s.z, dz, __low2float(k23));
        s.w = fmaf(s.w, dw, __high2float(k23));
    }
    reinterpret_cast<float4*>(g_e + (size_t)(b * NC_ + j) * C_)[t] = s;
}

// ============================================================
// 5) Carry propagation, batched independent loads
// ============================================================
__global__ __launch_bounds__(256) void scan_carry_kernel(const float* __restrict__ td) {
    int b = blockIdx.x, c = threadIdx.x;
    float r  = fmaxf(td[c], 0.f);
    float dL = expf(-r * (float)L_);
    float cy = 0.f;
    for (int jb = 0; jb < NC_; jb += 8) {
        float e[8];
        #pragma unroll
        for (int u = 0; u < 8; u++) e[u] = g_e[(size_t)(b * NC_ + jb + u) * C_ + c];
        #pragma unroll
        for (int u = 0; u < 8; u++) {
            g_carry[(size_t)(b * NC_ + jb + u) * C_ + c] = cy;
            cy = fmaf(dL, cy, e[u]);
        }
    }
}

// ============================================================
// 6) Scan pass 2 + y = r*(s+v) -> fp16
// ============================================================
__global__ __launch_bounds__(256) void scan2_kernel(const float* __restrict__ td) {
    int sub = threadIdx.x >> 6, t = threadIdx.x & 63;
    int j = blockIdx.x * 4 + sub, b = blockIdx.y;
    int c0 = t * 4;
    float4 tdv = *reinterpret_cast<const float4*>(td + c0);
    float dx = expf(-fmaxf(tdv.x, 0.f)), dy = expf(-fmaxf(tdv.y, 0.f));
    float dz = expf(-fmaxf(tdv.z, 0.f)), dw = expf(-fmaxf(tdv.w, 0.f));
    size_t base = ((size_t)(b * N_ + j * L_)) * C_ + c0;
    float4 s = reinterpret_cast<const float4*>(g_carry + (size_t)(b * NC_ + j) * C_)[t];
    #pragma unroll 4
    for (int i = 0; i < L_; i++) {
        size_t off = base + (size_t)i * C_;
        uint2 kraw = *reinterpret_cast<const uint2*>(&g_kvr[off]);
        uint2 vraw = *reinterpret_cast<const uint2*>(&g_kvr[MC_ + off]);
        uint2 rraw = *reinterpret_cast<const uint2*>(&g_kvr[2 * MC_ + off]);
        __half2 k01 = *reinterpret_cast<__half2*>(&kraw.x);
        __half2 k23 = *reinterpret_cast<__half2*>(&kraw.y);
        __half2 v01 = *reinterpret_cast<__half2*>(&vraw.x);
        __half2 v23 = *reinterpret_cast<__half2*>(&vraw.y);
        __half2 r01 = *reinterpret_cast<__half2*>(&rraw.x);
        __half2 r23 = *reinterpret_cast<__half2*>(&rraw.y);
        s.x = fmaf(s.x, dx, __low2float(k01));
        s.y = fmaf(s.y, dy, __high2float(k01));
        s.z = fmaf(s.z, dz, __low2float(k23));
        s.w = fmaf(s.w, dw, __high2float(k23));
        float y0 = __low2float(r01)  * (s.x + __low2float(v01));
        float y1 = __high2float(r01) * (s.y + __high2float(v01));
        float y2 = __low2float(r23)  * (s.z + __low2float(v23));
        float y3 = __high2float(r23) * (s.w + __high2float(v23));
        union { __half2 h2[2]; uint2 u; } Y;
        Y.h2[0] = __floats2half2_rn(y0, y1);
        Y.h2[1] = __floats2half2_rn(y2, y3);
        *reinterpret_cast<uint2*>(&g_ya[off]) = Y.u;
    }
}

// ============================================================
// launch
// ============================================================
extern "C" void kernel_launch(void* const* d_in, const int* in_sizes, int n_in,
                              void* d_out, int out_size) {
    const float* x   = (const float*)d_in[0];
    const float* td  = (const float*)d_in[1];
    const float* Wk  = (const float*)d_in[2];
    const float* Wv  = (const float*)d_in[3];
    const float* Wr  = (const float*)d_in[4];
    const float* Wo  = (const float*)d_in[5];
    const float* lnw = (const float*)d_in[6];
    const float* lnb = (const float*)d_in[7];
    float* out = (float*)d_out;

    __half *xa, *ya, *Wa, *Woa, *kvr;
    cudaGetSymbolAddress((void**)&xa,  g_xa);
    cudaGetSymbolAddress((void**)&ya,  g_ya);
    cudaGetSymbolAddress((void**)&Wa,  g_Wa);
    cudaGetSymbolAddress((void**)&Woa, g_Woa);
    cudaGetSymbolAddress((void**)&kvr, g_kvr);

    cudaFuncSetAttribute(mma_gemm_kernel,
                         cudaFuncAttributeMaxDynamicSharedMemorySize, SMEM_REQ);

    ln_kernel<<<M_ / 8, 256>>>(x, lnw, lnb);
    wconv_kernel<<<1024, 256>>>(Wk, Wv, Wr, Wo);
    // z=0 -> k, z=1 -> v, z=2 -> sigmoid(r); all fp16
    mma_gemm_kernel<<<dim3((C_ / BN) * 3, M_ / BM), 256, SMEM_REQ>>>(
        xa, Wa, nullptr, kvr, 3, 2);
    scan1_kernel<<<dim3(NC_ / 4, B_), 256>>>(td);
    scan_carry_kernel<<<B_, 256>>>(td);
    scan2_kernel<<<dim3(NC_ / 4, B_), 256>>>(td);
    // output GEMM -> fp32
    mma_gemm_kernel<<<dim3(C_ / BN, M_ / BM), 256, SMEM_REQ>>>(
        ya, Woa, out, nullptr, 1, -1);
}

// round 12
// speedup vs baseline: 1.4686x; 1.0009x over previous
#include <cuda_runtime.h>
#include <cuda_fp16.h>
#include <math.h>
#include <stdint.h>

#define B_  8
#define N_  16384
#define C_  256
#define M_  (B_*N_)      // 131072 rows
#define MC_ ((size_t)M_*C_)
#define L_  128          // scan chunk length == BM
#define NC_ (N_/L_)      // 128 chunks per batch

// ---- GEMM tiling ----
#define BM 128
#define BN 128
#define KCH 64
#define NKC (C_/KCH)           // 4
#define SAS 72                 // smem row stride in halves (144B)
#define A_B (BM*SAS*2)         // 18432
#define B_B (BN*SAS*2)         // 18432
#define STAGE_B (A_B + B_B)    // 36864
#define SMEM_REQ (2*STAGE_B)   // 73728
#define SDS 136                // fp16 staging stride (halves; 272B rows, 16B-aligned)
#define SDF 132                // fp32 staging stride (floats; 528B rows, 16B-aligned)

// ---- scratch ----
__device__ __half g_kvr[3*MC_];        // k, v, r  (fp16)
__device__ __half g_xa[MC_];           // LN(x) fp16
__device__ __half g_ya[MC_];           // y fp16
__device__ __half g_Wa[3*C_*C_];       // Wk,Wv,Wr fp16
__device__ __half g_Woa[C_*C_];        // Wo fp16
__device__ float  g_e[B_*NC_*C_];      // chunk-local end states
__device__ float  g_carry[B_*NC_*C_];  // injected carries

// ============================================================
// helpers
// ============================================================
__device__ __forceinline__ uint32_t smem_u32(const void* p) {
    return (uint32_t)__cvta_generic_to_shared(p);
}
__device__ __forceinline__ void ldm_x4(uint32_t* r, uint32_t addr) {
    asm volatile("ldmatrix.sync.aligned.m8n8.x4.shared.b16 {%0,%1,%2,%3}, [%4];"
                 : "=r"(r[0]), "=r"(r[1]), "=r"(r[2]), "=r"(r[3]) : "r"(addr));
}
__device__ __forceinline__ void mma16816(float* c, const uint32_t* a,
                                         uint32_t b0, uint32_t b1) {
    asm volatile(
        "mma.sync.aligned.m16n8k16.row.col.f32.f16.f16.f32 "
        "{%0,%1,%2,%3}, {%4,%5,%6,%7}, {%8,%9}, {%0,%1,%2,%3};"
        : "+f"(c[0]), "+f"(c[1]), "+f"(c[2]), "+f"(c[3])
        : "r"(a[0]), "r"(a[1]), "r"(a[2]), "r"(a[3]), "r"(b0), "r"(b1));
}
__device__ __forceinline__ void cp16(uint32_t sm, const void* g) {
    asm volatile("cp.async.cg.shared.global [%0], [%1], 16;" :: "r"(sm), "l"(g));
}
__device__ __forceinline__ void cp_commit() {
    asm volatile("cp.async.commit_group;");
}
template <int N>
__device__ __forceinline__ void cp_wait() {
    asm volatile("cp.async.wait_group %0;" :: "n"(N));
}

// ============================================================
// 1) LayerNorm -> fp16
// ============================================================
__global__ __launch_bounds__(256) void ln_kernel(
    const float* __restrict__ x,
    const float* __restrict__ lnw, const float* __restrict__ lnb)
{
    int row  = blockIdx.x * 8 + (threadIdx.x >> 5);
    int lane = threadIdx.x & 31;
    int c0   = lane * 8;
    const float4* xr = reinterpret_cast<const float4*>(x + (size_t)row * C_ + c0);
    float4 f0 = xr[0], f1 = xr[1];
    float v[8] = {f0.x, f0.y, f0.z, f0.w, f1.x, f1.y, f1.z, f1.w};

    float s = 0.f, s2 = 0.f;
    #pragma unroll
    for (int j = 0; j < 8; j++) { s += v[j]; s2 += v[j] * v[j]; }
    #pragma unroll
    for (int o = 16; o > 0; o >>= 1) {
        s  += __shfl_xor_sync(0xffffffffu, s,  o);
        s2 += __shfl_xor_sync(0xffffffffu, s2, o);
    }
    float mu   = s * (1.0f / C_);
    float var  = s2 * (1.0f / C_) - mu * mu;
    float rstd = rsqrtf(var + 1e-5f);

    union { __half h[8]; uint4 u; } ha;
    #pragma unroll
    for (int j = 0; j < 8; j++) {
        float xn = (v[j] - mu) * rstd * lnw[c0 + j] + lnb[c0 + j];
        ha.h[j] = __float2half_rn(xn);
    }
    *reinterpret_cast<uint4*>(&g_xa[(size_t)row * C_ + c0]) = ha.u;
}

// ============================================================
// 2) Weight convert -> fp16
// ============================================================
__global__ __launch_bounds__(256) void wconv_kernel(
    const float* __restrict__ Wk, const float* __restrict__ Wv,
    const float* __restrict__ Wr, const float* __restrict__ Wo)
{
    int idx = blockIdx.x * 256 + threadIdx.x;
    int mat = idx >> 16, rem = idx & 65535;
    float val = (mat == 0) ? Wk[rem] : (mat == 1) ? Wv[rem]
              : (mat == 2) ? Wr[rem] : Wo[rem];
    __half h = __float2half_rn(val);
    if (mat < 3) g_Wa[idx] = h;
    else         g_Woa[rem] = h;
}

// ============================================================
// 3) fp16 mma.sync GEMM.  Block 128x128, warp tile 32x64,
//    cp.async double-buffered over K=256, smem-staged epilogue.
//    z==0 with td != null additionally computes the chunk-local
//    scan of its k tile (m-tile == scan chunk) into g_e.
// ============================================================
__global__ void __launch_bounds__(256, 2) mma_gemm_kernel(
    const __half* __restrict__ A, const __half* __restrict__ W,
    float* __restrict__ outF, __half* __restrict__ outH,
    int nz, int sig_z, const float* __restrict__ td)
{
    extern __shared__ __half sm[];
    uint32_t sbase = smem_u32(sm);

    int zc = blockIdx.x;
    int z  = zc % nz;
    int ny = zc / nz;
    size_t m0 = (size_t)blockIdx.y * BM;
    int n0 = ny * BN;
    const __half* w = W + (size_t)z * C_ * C_;

    int tid = threadIdx.x;
    int warp = tid >> 5, lane = tid & 31;
    int wm = (warp & 3) * 32;          // 4 m-warps
    int wn = (warp >> 2) * 64;         // 2 n-warps
    int gID = lane >> 2, tig = lane & 3;

    float acc[2][8][4];
    #pragma unroll
    for (int i = 0; i < 2; i++)
        #pragma unroll
        for (int j = 0; j < 8; j++)
            #pragma unroll
            for (int q = 0; q < 4; q++) acc[i][j][q] = 0.f;

    int arow  = lane & 15;
    int acolo = (lane >> 4) << 3;
    int q4 = lane >> 3;
    int brow_in = (lane & 7) + ((q4 >> 1) << 3);
    int bcolo = (q4 & 1) << 3;

    auto load_chunk = [&](int kc, int stg) {
        uint32_t base = sbase + stg * STAGE_B;
        int k0 = kc * KCH;
        #pragma unroll
        for (int it = 0; it < 4; it++) {          // A: 1024 vec16
            int v = it * 256 + tid;
            int r = v >> 3, cv = v & 7;
            cp16(base + r * (SAS * 2) + cv * 16,
                 A + (m0 + r) * C_ + k0 + cv * 8);
        }
        #pragma unroll
        for (int it = 0; it < 4; it++) {          // B: 1024 vec16
            int v = it * 256 + tid;
            int r = v >> 3, cv = v & 7;
            cp16(base + A_B + r * (SAS * 2) + cv * 16,
                 w + (size_t)(n0 + r) * C_ + k0 + cv * 8);
        }
        cp_commit();
    };

    load_chunk(0, 0);

    for (int kc = 0; kc < NKC; kc++) {
        cp_wait<0>();
        __syncthreads();
        if (kc + 1 < NKC) load_chunk(kc + 1, (kc + 1) & 1);

        uint32_t base = sbase + (kc & 1) * STAGE_B;
        uint32_t aB = base, bB = base + A_B;

        #pragma unroll
        for (int ks = 0; ks < KCH / 16; ks++) {
            int kk = ks * 16;
            uint32_t a[2][4], b[4][4];
            #pragma unroll
            for (int i = 0; i < 2; i++)
                ldm_x4(a[i], aB + (wm + i * 16 + arow) * (SAS * 2) + (kk + acolo) * 2);
            #pragma unroll
            for (int p = 0; p < 4; p++)
                ldm_x4(b[p], bB + (wn + p * 16 + brow_in) * (SAS * 2) + (kk + bcolo) * 2);
            #pragma unroll
            for (int i = 0; i < 2; i++)
                #pragma unroll
                for (int j = 0; j < 8; j++) {
                    int p = j >> 1, o = (j & 1) * 2;
                    mma16816(acc[i][j], a[i], b[p][o], b[p][o + 1]);
                }
        }
    }
    __syncthreads();   // done with stage buffers; reuse as staging

    if (outF) {
        // ---- fp32 staging + coalesced copy ----
        float* sD = reinterpret_cast<float*>(sm);
        #pragma unroll
        for (int i = 0; i < 2; i++) {
            int row = wm + i * 16 + gID;
            #pragma unroll
            for (int j = 0; j < 8; j++) {
                int col = wn + j * 8 + tig * 2;
                *reinterpret_cast<float2*>(&sD[row * SDF + col]) =
                    make_float2(acc[i][j][0], acc[i][j][1]);
                *reinterpret_cast<float2*>(&sD[(row + 8) * SDF + col]) =
                    make_float2(acc[i][j][2], acc[i][j][3]);
            }
        }
        __syncthreads();
        #pragma unroll
        for (int it = 0; it < 16; it++) {         // 128 rows x 32 seg16B
            int idx = it * 256 + tid;
            int row = idx >> 5, seg = idx & 31;
            float4 v = *reinterpret_cast<float4*>(&sD[row * SDF + seg * 4]);
            *reinterpret_cast<float4*>(&outF[(m0 + row) * C_ + n0 + seg * 4]) = v;
        }
    } else {
        // ---- fp16 staging + coalesced copy ----
        bool sig = (z == sig_z);
        __half* sD = sm;
        #pragma unroll
        for (int i = 0; i < 2; i++) {
            int row = wm + i * 16 + gID;
            #pragma unroll
            for (int j = 0; j < 8; j++) {
                int col = wn + j * 8 + tig * 2;
                float v0 = acc[i][j][0], v1 = acc[i][j][1];
                float v2 = acc[i][j][2], v3 = acc[i][j][3];
                if (sig) {
                    v0 = 1.0f / (1.0f + __expf(-v0));
                    v1 = 1.0f / (1.0f + __expf(-v1));
                    v2 = 1.0f / (1.0f + __expf(-v2));
                    v3 = 1.0f / (1.0f + __expf(-v3));
                }
                *reinterpret_cast<__half2*>(&sD[row * SDS + col]) =
                    __floats2half2_rn(v0, v1);
                *reinterpret_cast<__half2*>(&sD[(row + 8) * SDS + col]) =
                    __floats2half2_rn(v2, v3);
            }
        }
        __syncthreads();
        __half* oh = outH + (size_t)z * MC_;
        #pragma unroll
        for (int it = 0; it < 8; it++) {          // 128 rows x 16 seg16B
            int idx = it * 256 + tid;
            int row = idx >> 4, seg = idx & 15;
            uint4 v = *reinterpret_cast<uint4*>(&sD[row * SDS + seg * 8]);
            *reinterpret_cast<uint4*>(&oh[(m0 + row) * C_ + n0 + seg * 8]) = v;
        }

        // ---- fused chunk-local scan for the k matrix (z == 0) ----
        // m-tile == scan chunk: rows are timesteps, cols are channels.
        if (z == 0 && td) {
            int ch = tid & 127, half = tid >> 7;
            int m0i = (int)m0;
            int b  = m0i >> 14;            // / N_
            int jc = (m0i & (N_ - 1)) >> 7; // chunk index within batch
            float rr = fmaxf(td[n0 + ch], 0.f);
            float d  = __expf(-rr);
            float s = 0.f;
            int i0 = half * 64;
            #pragma unroll 8
            for (int i = 0; i < 64; i++)
                s = fmaf(s, d, __half2float(sD[(i0 + i) * SDS + ch]));
            float* part = reinterpret_cast<float*>(sm + 20480);  // byte 40960, past staging
            part[tid] = s;
            __syncthreads();
            if (half == 0) {
                float d64 = __expf(-rr * 64.f);
                float e = fmaf(d64, s, part[128 + ch]);  // e1 + d^64 * e0
                g_e[((size_t)(b * NC_ + jc)) * C_ + n0 + ch] = e;
            }
        }
    }
}

// ============================================================
// 4) Carry propagation, batched independent loads
// ============================================================
__global__ __launch_bounds__(256) void scan_carry_kernel(const float* __restrict__ td) {
    int b = blockIdx.x, c = threadIdx.x;
    float r  = fmaxf(td[c], 0.f);
    float dL = expf(-r * (float)L_);
    float cy = 0.f;
    for (int jb = 0; jb < NC_; jb += 8) {
        float e[8];
        #pragma unroll
        for (int u = 0; u < 8; u++) e[u] = g_e[(size_t)(b * NC_ + jb + u) * C_ + c];
        #pragma unroll
        for (int u = 0; u < 8; u++) {
            g_carry[(size_t)(b * NC_ + jb + u) * C_ + c] = cy;
            cy = fmaf(dL, cy, e[u]);
        }
    }
}

// ============================================================
// 5) Scan pass 2 + y = r*(s+v) -> fp16.
//    grid (NC_, B_), 128 threads, 2 channels/thread.
// ============================================================
__global__ __launch_bounds__(128) void scan2_kernel(const float* __restrict__ td) {
    int j = blockIdx.x, b = blockIdx.y;
    int t = threadIdx.x;
    int c0 = t * 2;
    float2 tdv = *reinterpret_cast<const float2*>(td + c0);
    float dx = expf(-fmaxf(tdv.x, 0.f)), dy = expf(-fmaxf(tdv.y, 0.f));
    size_t base = ((size_t)(b * N_ + j * L_)) * C_ + c0;
    float2 s = *reinterpret_cast<const float2*>(
        g_carry + (size_t)(b * NC_ + j) * C_ + c0);
    #pragma unroll 8
    for (int i = 0; i < L_; i++) {
        size_t off = base + (size_t)i * C_;
        uint32_t kraw = *reinterpret_cast<const uint32_t*>(&g_kvr[off]);
        uint32_t vraw = *reinterpret_cast<const uint32_t*>(&g_kvr[MC_ + off]);
        uint32_t rraw = *reinterpret_cast<const uint32_t*>(&g_kvr[2 * MC_ + off]);
        __half2 kk = *reinterpret_cast<__half2*>(&kraw);
        __half2 vv = *reinterpret_cast<__half2*>(&vraw);
        __half2 rg = *reinterpret_cast<__half2*>(&rraw);
        s.x = fmaf(s.x, dx, __low2float(kk));
        s.y = fmaf(s.y, dy, __high2float(kk));
        float y0 = __low2float(rg)  * (s.x + __low2float(vv));
        float y1 = __high2float(rg) * (s.y + __high2float(vv));
        union { __half2 h2; uint32_t u; } Y;
        Y.h2 = __floats2half2_rn(y0, y1);
        *reinterpret_cast<uint32_t*>(&g_ya[off]) = Y.u;
    }
}

// ============================================================
// launch
// ============================================================
extern "C" void kernel_launch(void* const* d_in, const int* in_sizes, int n_in,
                              void* d_out, int out_size) {
    const float* x   = (const float*)d_in[0];
    const float* td  = (const float*)d_in[1];
    const float* Wk  = (const float*)d_in[2];
    const float* Wv  = (const float*)d_in[3];
    const float* Wr  = (const float*)d_in[4];
    const float* Wo  = (const float*)d_in[5];
    const float* lnw = (const float*)d_in[6];
    const float* lnb = (const float*)d_in[7];
    float* out = (float*)d_out;

    __half *xa, *ya, *Wa, *Woa, *kvr;
    cudaGetSymbolAddress((void**)&xa,  g_xa);
    cudaGetSymbolAddress((void**)&ya,  g_ya);
    cudaGetSymbolAddress((void**)&Wa,  g_Wa);
    cudaGetSymbolAddress((void**)&Woa, g_Woa);
    cudaGetSymbolAddress((void**)&kvr, g_kvr);

    cudaFuncSetAttribute(mma_gemm_kernel,
                         cudaFuncAttributeMaxDynamicSharedMemorySize, SMEM_REQ);

    ln_kernel<<<M_ / 8, 256>>>(x, lnw, lnb);
    wconv_kernel<<<1024, 256>>>(Wk, Wv, Wr, Wo);
    // z=0 -> k (+fused chunk scan), z=1 -> v, z=2 -> sigmoid(r)
    mma_gemm_kernel<<<dim3((C_ / BN) * 3, M_ / BM), 256, SMEM_REQ>>>(
        xa, Wa, nullptr, kvr, 3, 2, td);
    scan_carry_kernel<<<B_, 256>>>(td);
    scan2_kernel<<<dim3(NC_, B_), 128>>>(td);
    // output GEMM -> fp32
    mma_gemm_kernel<<<dim3(C_ / BN, M_ / BM), 256, SMEM_REQ>>>(
        ya, Woa, out, nullptr, 1, -1, nullptr);
}

// round 15
// speedup vs baseline: 1.5517x; 1.0566x over previous
#include <cuda_runtime.h>
#include <cuda_fp16.h>
#include <math.h>
#include <stdint.h>

#define B_  8
#define N_  16384
#define C_  256
#define M_  (B_*N_)      // 131072 rows
#define MC_ ((size_t)M_*C_)
#define L_  128          // scan chunk length == BM
#define NC_ (N_/L_)      // 128 chunks per batch

// ---- GEMM tiling ----
#define BM 128
#define BN 128
#define KCH 64
#define NKC (C_/KCH)           // 4
#define SAS 72                 // smem row stride in halves (144B)
#define A_B (BM*SAS*2)         // 18432
#define B_B (BN*SAS*2)         // 18432
#define STAGE_B (A_B + B_B)    // 36864
#define NSTG 3
#define SMEM_REQ (NSTG*STAGE_B)   // 110592
#define SDS 136                // fp16 staging stride (halves; 272B rows, 16B-aligned)
#define SDF 132                // fp32 staging stride (floats; 528B rows, 16B-aligned)

// ---- scratch ----
__device__ __half g_kvr[3*MC_];        // k, v, r  (fp16)
__device__ __half g_xa[MC_];           // LN(x) fp16
__device__ __half g_ya[MC_];           // y fp16
__device__ __half g_Wa[3*C_*C_];       // Wk,Wv,Wr fp16
__device__ __half g_Woa[C_*C_];        // Wo fp16
__device__ float  g_e[B_*NC_*C_];      // chunk-local end states
__device__ float  g_carry[B_*NC_*C_];  // injected carries

// ============================================================
// helpers
// ============================================================
__device__ __forceinline__ uint32_t smem_u32(const void* p) {
    return (uint32_t)__cvta_generic_to_shared(p);
}
__device__ __forceinline__ void ldm_x4(uint32_t* r, uint32_t addr) {
    asm volatile("ldmatrix.sync.aligned.m8n8.x4.shared.b16 {%0,%1,%2,%3}, [%4];"
                 : "=r"(r[0]), "=r"(r[1]), "=r"(r[2]), "=r"(r[3]) : "r"(addr));
}
__device__ __forceinline__ void mma16816(float* c, const uint32_t* a,
                                         uint32_t b0, uint32_t b1) {
    asm volatile(
        "mma.sync.aligned.m16n8k16.row.col.f32.f16.f16.f32 "
        "{%0,%1,%2,%3}, {%4,%5,%6,%7}, {%8,%9}, {%0,%1,%2,%3};"
        : "+f"(c[0]), "+f"(c[1]), "+f"(c[2]), "+f"(c[3])
        : "r"(a[0]), "r"(a[1]), "r"(a[2]), "r"(a[3]), "r"(b0), "r"(b1));
}
__device__ __forceinline__ void cp16(uint32_t sm, const void* g) {
    asm volatile("cp.async.cg.shared.global [%0], [%1], 16;" :: "r"(sm), "l"(g));
}
__device__ __forceinline__ void cp_commit() {
    asm volatile("cp.async.commit_group;");
}
template <int N>
__device__ __forceinline__ void cp_wait() {
    asm volatile("cp.async.wait_group %0;" :: "n"(N));
}

// ============================================================
// 1) Merged LayerNorm->fp16  +  weight convert->fp16
//    blocks [0, M_/8)            : LN
//    blocks [M_/8, M_/8 + 1024)  : weight convert
// ============================================================
__global__ __launch_bounds__(256) void prep_kernel(
    const float* __restrict__ x,
    const float* __restrict__ lnw, const float* __restrict__ lnb,
    const float* __restrict__ Wk, const float* __restrict__ Wv,
    const float* __restrict__ Wr, const float* __restrict__ Wo)
{
    if (blockIdx.x < M_ / 8) {
        int row  = blockIdx.x * 8 + (threadIdx.x >> 5);
        int lane = threadIdx.x & 31;
        int c0   = lane * 8;
        const float4* xr = reinterpret_cast<const float4*>(x + (size_t)row * C_ + c0);
        float4 f0 = xr[0], f1 = xr[1];
        float v[8] = {f0.x, f0.y, f0.z, f0.w, f1.x, f1.y, f1.z, f1.w};

        float s = 0.f, s2 = 0.f;
        #pragma unroll
        for (int j = 0; j < 8; j++) { s += v[j]; s2 += v[j] * v[j]; }
        #pragma unroll
        for (int o = 16; o > 0; o >>= 1) {
            s  += __shfl_xor_sync(0xffffffffu, s,  o);
            s2 += __shfl_xor_sync(0xffffffffu, s2, o);
        }
        float mu   = s * (1.0f / C_);
        float var  = s2 * (1.0f / C_) - mu * mu;
        float rstd = rsqrtf(var + 1e-5f);

        union { __half h[8]; uint4 u; } ha;
        #pragma unroll
        for (int j = 0; j < 8; j++) {
            float xn = (v[j] - mu) * rstd * lnw[c0 + j] + lnb[c0 + j];
            ha.h[j] = __float2half_rn(xn);
        }
        *reinterpret_cast<uint4*>(&g_xa[(size_t)row * C_ + c0]) = ha.u;
    } else {
        int idx = (blockIdx.x - M_ / 8) * 256 + threadIdx.x;
        int mat = idx >> 16, rem = idx & 65535;
        float val = (mat == 0) ? Wk[rem] : (mat == 1) ? Wv[rem]
                  : (mat == 2) ? Wr[rem] : Wo[rem];
        __half h = __float2half_rn(val);
        if (mat < 3) g_Wa[idx] = h;
        else         g_Woa[rem] = h;
    }
}

// ============================================================
// 2) fp16 mma.sync GEMM.  Block 128x128, warp tile 32x64,
//    3-stage cp.async pipeline over K=256, smem-staged epilogue.
//    z==0 with td != null additionally computes the chunk-local
//    scan of its k tile (m-tile == scan chunk) into g_e.
// ============================================================
__global__ void __launch_bounds__(256, 2) mma_gemm_kernel(
    const __half* __restrict__ A, const __half* __restrict__ W,
    float* __restrict__ outF, __half* __restrict__ outH,
    int nz, int sig_z, const float* __restrict__ td)
{
    extern __shared__ __half sm[];
    uint32_t sbase = smem_u32(sm);

    int zc = blockIdx.x;
    int z  = zc % nz;
    int ny = zc / nz;
    size_t m0 = (size_t)blockIdx.y * BM;
    int n0 = ny * BN;
    const __half* w = W + (size_t)z * C_ * C_;

    int tid = threadIdx.x;
    int warp = tid >> 5, lane = tid & 31;
    int wm = (warp & 3) * 32;          // 4 m-warps
    int wn = (warp >> 2) * 64;         // 2 n-warps
    int gID = lane >> 2, tig = lane & 3;

    float acc[2][8][4];
    #pragma unroll
    for (int i = 0; i < 2; i++)
        #pragma unroll
        for (int j = 0; j < 8; j++)
            #pragma unroll
            for (int q = 0; q < 4; q++) acc[i][j][q] = 0.f;

    int arow  = lane & 15;
    int acolo = (lane >> 4) << 3;
    int q4 = lane >> 3;
    int brow_in = (lane & 7) + ((q4 >> 1) << 3);
    int bcolo = (q4 & 1) << 3;

    auto load_chunk = [&](int kc, int stg) {
        uint32_t base = sbase + stg * STAGE_B;
        int k0 = kc * KCH;
        #pragma unroll
        for (int it = 0; it < 4; it++) {          // A: 1024 vec16
            int v = it * 256 + tid;
            int r = v >> 3, cv = v & 7;
            cp16(base + r * (SAS * 2) + cv * 16,
                 A + (m0 + r) * C_ + k0 + cv * 8);
        }
        #pragma unroll
        for (int it = 0; it < 4; it++) {          // B: 1024 vec16
            int v = it * 256 + tid;
            int r = v >> 3, cv = v & 7;
            cp16(base + A_B + r * (SAS * 2) + cv * 16,
                 w + (size_t)(n0 + r) * C_ + k0 + cv * 8);
        }
        cp_commit();
    };

    load_chunk(0, 0);
    load_chunk(1, 1);

    for (int kc = 0; kc < NKC; kc++) {
        if (kc < NKC - 1) cp_wait<1>();
        else              cp_wait<0>();
        __syncthreads();
        if (kc + 2 < NKC) load_chunk(kc + 2, (kc + 2) % NSTG);

        uint32_t base = sbase + (kc % NSTG) * STAGE_B;
        uint32_t aB = base, bB = base + A_B;

        #pragma unroll
        for (int ks = 0; ks < KCH / 16; ks++) {
            int kk = ks * 16;
            uint32_t a[2][4], b[4][4];
            #pragma unroll
            for (int i = 0; i < 2; i++)
                ldm_x4(a[i], aB + (wm + i * 16 + arow) * (SAS * 2) + (kk + acolo) * 2);
            #pragma unroll
            for (int p = 0; p < 4; p++)
                ldm_x4(b[p], bB + (wn + p * 16 + brow_in) * (SAS * 2) + (kk + bcolo) * 2);
            #pragma unroll
            for (int i = 0; i < 2; i++)
                #pragma unroll
                for (int j = 0; j < 8; j++) {
                    int p = j >> 1, o = (j & 1) * 2;
                    mma16816(acc[i][j], a[i], b[p][o], b[p][o + 1]);
                }
        }
    }
    __syncthreads();   // done with stage buffers; reuse as staging

    if (outF) {
        // ---- fp32 staging + coalesced copy ----
        float* sD = reinterpret_cast<float*>(sm);
        #pragma unroll
        for (int i = 0; i < 2; i++) {
            int row = wm + i * 16 + gID;
            #pragma unroll
            for (int j = 0; j < 8; j++) {
                int col = wn + j * 8 + tig * 2;
                *reinterpret_cast<float2*>(&sD[row * SDF + col]) =
                    make_float2(acc[i][j][0], acc[i][j][1]);
                *reinterpret_cast<float2*>(&sD[(row + 8) * SDF + col]) =
                    make_float2(acc[i][j][2], acc[i][j][3]);
            }
        }
        __syncthreads();
        #pragma unroll
        for (int it = 0; it < 16; it++) {         // 128 rows x 32 seg16B
            int idx = it * 256 + tid;
            int row = idx >> 5, seg = idx & 31;
            float4 v = *reinterpret_cast<float4*>(&sD[row * SDF + seg * 4]);
            *reinterpret_cast<float4*>(&outF[(m0 + row) * C_ + n0 + seg * 4]) = v;
        }
    } else {
        // ---- fp16 staging + coalesced copy ----
        bool sig = (z == sig_z);
        __half* sD = sm;
        #pragma unroll
        for (int i = 0; i < 2; i++) {
            int row = wm + i * 16 + gID;
            #pragma unroll
            for (int j = 0; j < 8; j++) {
                int col = wn + j * 8 + tig * 2;
                float v0 = acc[i][j][0], v1 = acc[i][j][1];
                float v2 = acc[i][j][2], v3 = acc[i][j][3];
                if (sig) {
                    v0 = 1.0f / (1.0f + __expf(-v0));
                    v1 = 1.0f / (1.0f + __expf(-v1));
                    v2 = 1.0f / (1.0f + __expf(-v2));
                    v3 = 1.0f / (1.0f + __expf(-v3));
                }
                *reinterpret_cast<__half2*>(&sD[row * SDS + col]) =
                    __floats2half2_rn(v0, v1);
                *reinterpret_cast<__half2*>(&sD[(row + 8) * SDS + col]) =
                    __floats2half2_rn(v2, v3);
            }
        }
        __syncthreads();
        __half* oh = outH + (size_t)z * MC_;
        #pragma unroll
        for (int it = 0; it < 8; it++) {          // 128 rows x 16 seg16B
            int idx = it * 256 + tid;
            int row = idx >> 4, seg = idx & 15;
            uint4 v = *reinterpret_cast<uint4*>(&sD[row * SDS + seg * 8]);
            *reinterpret_cast<uint4*>(&oh[(m0 + row) * C_ + n0 + seg * 8]) = v;
        }

        // ---- fused chunk-local scan for the k matrix (z == 0) ----
        if (z == 0 && td) {
            int ch = tid & 127, half = tid >> 7;
            int m0i = (int)m0;
            int b  = m0i >> 14;             // / N_
            int jc = (m0i & (N_ - 1)) >> 7; // chunk index within batch
            float rr = fmaxf(td[n0 + ch], 0.f);
            float d  = __expf(-rr);
            float s = 0.f;
            int i0 = half * 64;
            #pragma unroll 8
            for (int i = 0; i < 64; i++)
                s = fmaf(s, d, __half2float(sD[(i0 + i) * SDS + ch]));
            float* part = reinterpret_cast<float*>(sm + 20480);  // byte 40960
            part[tid] = s;
            __syncthreads();
            if (half == 0) {
                float d64 = __expf(-rr * 64.f);
                float e = fmaf(d64, s, part[128 + ch]);  // e1 + d^64 * e0
                g_e[((size_t)(b * NC_ + jc)) * C_ + n0 + ch] = e;
            }
        }
    }
}

// ============================================================
// 3) Carry propagation, 16-wide batched independent loads
// ============================================================
__global__ __launch_bounds__(256) void scan_carry_kernel(const float* __restrict__ td) {
    int b = blockIdx.x, c = threadIdx.x;
    float r  = fmaxf(td[c], 0.f);
    float dL = expf(-r * (float)L_);
    float cy = 0.f;
    for (int jb = 0; jb < NC_; jb += 16) {
        float e[16];
        #pragma unroll
        for (int u = 0; u < 16; u++) e[u] = g_e[(size_t)(b * NC_ + jb + u) * C_ + c];
        #pragma unroll
        for (int u = 0; u < 16; u++) {
            g_carry[(size_t)(b * NC_ + jb + u) * C_ + c] = cy;
            cy = fmaf(dL, cy, e[u]);
        }
    }
}

// ============================================================
// 4) Scan pass 2 + y = r*(s+v) -> fp16.
//    R11 config: grid (NC_/4, B_), 256 thr, 4 ch/thread, uint2 loads.
// ============================================================
__global__ __launch_bounds__(256) void scan2_kernel(const float* __restrict__ td) {
    int sub = threadIdx.x >> 6, t = threadIdx.x & 63;
    int j = blockIdx.x * 4 + sub, b = blockIdx.y;
    int c0 = t * 4;
    float4 tdv = *reinterpret_cast<const float4*>(td + c0);
    float dx = expf(-fmaxf(tdv.x, 0.f)), dy = expf(-fmaxf(tdv.y, 0.f));
    float dz = expf(-fmaxf(tdv.z, 0.f)), dw = expf(-fmaxf(tdv.w, 0.f));
    size_t base = ((size_t)(b * N_ + j * L_)) * C_ + c0;
    float4 s = reinterpret_cast<const float4*>(g_carry + (size_t)(b * NC_ + j) * C_)[t];
    #pragma unroll 4
    for (int i = 0; i < L_; i++) {
        size_t off = base + (size_t)i * C_;
        uint2 kraw = *reinterpret_cast<const uint2*>(&g_kvr[off]);
        uint2 vraw = *reinterpret_cast<const uint2*>(&g_kvr[MC_ + off]);
        uint2 rraw = *reinterpret_cast<const uint2*>(&g_kvr[2 * MC_ + off]);
        __half2 k01 = *reinterpret_cast<__half2*>(&kraw.x);
        __half2 k23 = *reinterpret_cast<__half2*>(&kraw.y);
        __half2 v01 = *reinterpret_cast<__half2*>(&vraw.x);
        __half2 v23 = *reinterpret_cast<__half2*>(&vraw.y);
        __half2 r01 = *reinterpret_cast<__half2*>(&rraw.x);
        __half2 r23 = *reinterpret_cast<__half2*>(&rraw.y);
        s.x = fmaf(s.x, dx, __low2float(k01));
        s.y = fmaf(s.y, dy, __high2float(k01));
        s.z = fmaf(s.z, dz, __low2float(k23));
        s.w = fmaf(s.w, dw, __high2float(k23));
        float y0 = __low2float(r01)  * (s.x + __low2float(v01));
        float y1 = __high2float(r01) * (s.y + __high2float(v01));
        float y2 = __low2float(r23)  * (s.z + __low2float(v23));
        float y3 = __high2float(r23) * (s.w + __high2float(v23));
        union { __half2 h2[2]; uint2 u; } Y;
        Y.h2[0] = __floats2half2_rn(y0, y1);
        Y.h2[1] = __floats2half2_rn(y2, y3);
        *reinterpret_cast<uint2*>(&g_ya[off]) = Y.u;
    }
}

// ============================================================
// launch
// ============================================================
extern "C" void kernel_launch(void* const* d_in, const int* in_sizes, int n_in,
                              void* d_out, int out_size) {
    const float* x   = (const float*)d_in[0];
    const float* td  = (const float*)d_in[1];
    const float* Wk  = (const float*)d_in[2];
    const float* Wv  = (const float*)d_in[3];
    const float* Wr  = (const float*)d_in[4];
    const float* Wo  = (const float*)d_in[5];
    const float* lnw = (const float*)d_in[6];
    const float* lnb = (const float*)d_in[7];
    float* out = (float*)d_out;

    __half *xa, *ya, *Wa, *Woa, *kvr;
    cudaGetSymbolAddress((void**)&xa,  g_xa);
    cudaGetSymbolAddress((void**)&ya,  g_ya);
    cudaGetSymbolAddress((void**)&Wa,  g_Wa);
    cudaGetSymbolAddress((void**)&Woa, g_Woa);
    cudaGetSymbolAddress((void**)&kvr, g_kvr);

    cudaFuncSetAttribute(mma_gemm_kernel,
                         cudaFuncAttributeMaxDynamicSharedMemorySize, SMEM_REQ);

    prep_kernel<<<M_ / 8 + 1024, 256>>>(x, lnw, lnb, Wk, Wv, Wr, Wo);
    // z=0 -> k (+fused chunk scan), z=1 -> v, z=2 -> sigmoid(r)
    mma_gemm_kernel<<<dim3((C_ / BN) * 3, M_ / BM), 256, SMEM_REQ>>>(
        xa, Wa, nullptr, kvr, 3, 2, td);
    scan_carry_kernel<<<B_, 256>>>(td);
    scan2_kernel<<<dim3(NC_ / 4, B_), 256>>>(td);
    // output GEMM -> fp32
    mma_gemm_kernel<<<dim3(C_ / BN, M_ / BM), 256, SMEM_REQ>>>(
        ya, Woa, out, nullptr, 1, -1, nullptr);
}

// round 16
// speedup vs baseline: 1.6712x; 1.0770x over previous
#include <cuda_runtime.h>
#include <cuda_fp16.h>
#include <math.h>
#include <stdint.h>

#define B_  8
#define N_  16384
#define C_  256
#define M_  (B_*N_)      // 131072 rows
#define MC_ ((size_t)M_*C_)
#define SEG 32           // scan segment length
#define NSG (N_/SEG)     // 512 segments per batch
#define NC_ 128          // GEMM m-tiles per batch (BM=128)

// ---- GEMM tiling ----
#define BM 128
#define BN 128
#define KCH 64
#define NKC (C_/KCH)           // 4
#define SAS 72                 // smem row stride in halves (144B)
#define A_B (BM*SAS*2)         // 18432
#define B_B (BN*SAS*2)         // 18432
#define STAGE_B (A_B + B_B)    // 36864
#define NSTG 3
#define SMEM_REQ (NSTG*STAGE_B)   // 110592
#define SDS 136                // fp16 staging stride (halves; 272B rows, 16B-aligned)
#define SDF 132                // fp32 staging stride (floats; 528B rows, 16B-aligned)

// ---- scratch ----
__device__ __half g_kvr[3*MC_];        // k, v, r  (fp16)
__device__ __half g_xa[MC_];           // LN(x) fp16
__device__ __half g_ya[MC_];           // y fp16
__device__ __half g_Wa[3*C_*C_];       // Wk,Wv,Wr fp16
__device__ __half g_Woa[C_*C_];        // Wo fp16
__device__ float  g_e[B_*NSG*C_];      // segment-local end states (32-step)
__device__ float  g_carry[B_*NSG*C_];  // injected carries per segment

// ============================================================
// helpers
// ============================================================
__device__ __forceinline__ uint32_t smem_u32(const void* p) {
    return (uint32_t)__cvta_generic_to_shared(p);
}
__device__ __forceinline__ void ldm_x4(uint32_t* r, uint32_t addr) {
    asm volatile("ldmatrix.sync.aligned.m8n8.x4.shared.b16 {%0,%1,%2,%3}, [%4];"
                 : "=r"(r[0]), "=r"(r[1]), "=r"(r[2]), "=r"(r[3]) : "r"(addr));
}
__device__ __forceinline__ void mma16816(float* c, const uint32_t* a,
                                         uint32_t b0, uint32_t b1) {
    asm volatile(
        "mma.sync.aligned.m16n8k16.row.col.f32.f16.f16.f32 "
        "{%0,%1,%2,%3}, {%4,%5,%6,%7}, {%8,%9}, {%0,%1,%2,%3};"
        : "+f"(c[0]), "+f"(c[1]), "+f"(c[2]), "+f"(c[3])
        : "r"(a[0]), "r"(a[1]), "r"(a[2]), "r"(a[3]), "r"(b0), "r"(b1));
}
__device__ __forceinline__ void cp16(uint32_t sm, const void* g) {
    asm volatile("cp.async.cg.shared.global [%0], [%1], 16;" :: "r"(sm), "l"(g));
}
__device__ __forceinline__ void cp_commit() {
    asm volatile("cp.async.commit_group;");
}
template <int N>
__device__ __forceinline__ void cp_wait() {
    asm volatile("cp.async.wait_group %0;" :: "n"(N));
}

// ============================================================
// 1) Merged LayerNorm->fp16  +  weight convert->fp16
// ============================================================
__global__ __launch_bounds__(256) void prep_kernel(
    const float* __restrict__ x,
    const float* __restrict__ lnw, const float* __restrict__ lnb,
    const float* __restrict__ Wk, const float* __restrict__ Wv,
    const float* __restrict__ Wr, const float* __restrict__ Wo)
{
    if (blockIdx.x < M_ / 8) {
        int row  = blockIdx.x * 8 + (threadIdx.x >> 5);
        int lane = threadIdx.x & 31;
        int c0   = lane * 8;
        const float4* xr = reinterpret_cast<const float4*>(x + (size_t)row * C_ + c0);
        float4 f0 = xr[0], f1 = xr[1];
        float v[8] = {f0.x, f0.y, f0.z, f0.w, f1.x, f1.y, f1.z, f1.w};

        float s = 0.f, s2 = 0.f;
        #pragma unroll
        for (int j = 0; j < 8; j++) { s += v[j]; s2 += v[j] * v[j]; }
        #pragma unroll
        for (int o = 16; o > 0; o >>= 1) {
            s  += __shfl_xor_sync(0xffffffffu, s,  o);
            s2 += __shfl_xor_sync(0xffffffffu, s2, o);
        }
        float mu   = s * (1.0f / C_);
        float var  = s2 * (1.0f / C_) - mu * mu;
        float rstd = rsqrtf(var + 1e-5f);

        union { __half h[8]; uint4 u; } ha;
        #pragma unroll
        for (int j = 0; j < 8; j++) {
            float xn = (v[j] - mu) * rstd * lnw[c0 + j] + lnb[c0 + j];
            ha.h[j] = __float2half_rn(xn);
        }
        *reinterpret_cast<uint4*>(&g_xa[(size_t)row * C_ + c0]) = ha.u;
    } else {
        int idx = (blockIdx.x - M_ / 8) * 256 + threadIdx.x;
        int mat = idx >> 16, rem = idx & 65535;
        float val = (mat == 0) ? Wk[rem] : (mat == 1) ? Wv[rem]
                  : (mat == 2) ? Wr[rem] : Wo[rem];
        __half h = __float2half_rn(val);
        if (mat < 3) g_Wa[idx] = h;
        else         g_Woa[rem] = h;
    }
}

// ============================================================
// 2) fp16 mma.sync GEMM.  Block 128x128, warp tile 32x64,
//    3-stage cp.async pipeline, smem-staged epilogue.
//    z==0 with td != null also emits 32-step segment scans of
//    its k tile (4 segments per m-tile) into g_e.
// ============================================================
__global__ void __launch_bounds__(256, 2) mma_gemm_kernel(
    const __half* __restrict__ A, const __half* __restrict__ W,
    float* __restrict__ outF, __half* __restrict__ outH,
    int nz, int sig_z, const float* __restrict__ td)
{
    extern __shared__ __half sm[];
    uint32_t sbase = smem_u32(sm);

    int zc = blockIdx.x;
    int z  = zc % nz;
    int ny = zc / nz;
    size_t m0 = (size_t)blockIdx.y * BM;
    int n0 = ny * BN;
    const __half* w = W + (size_t)z * C_ * C_;

    int tid = threadIdx.x;
    int warp = tid >> 5, lane = tid & 31;
    int wm = (warp & 3) * 32;
    int wn = (warp >> 2) * 64;
    int gID = lane >> 2, tig = lane & 3;

    float acc[2][8][4];
    #pragma unroll
    for (int i = 0; i < 2; i++)
        #pragma unroll
        for (int j = 0; j < 8; j++)
            #pragma unroll
            for (int q = 0; q < 4; q++) acc[i][j][q] = 0.f;

    int arow  = lane & 15;
    int acolo = (lane >> 4) << 3;
    int q4 = lane >> 3;
    int brow_in = (lane & 7) + ((q4 >> 1) << 3);
    int bcolo = (q4 & 1) << 3;

    auto load_chunk = [&](int kc, int stg) {
        uint32_t base = sbase + stg * STAGE_B;
        int k0 = kc * KCH;
        #pragma unroll
        for (int it = 0; it < 4; it++) {
            int v = it * 256 + tid;
            int r = v >> 3, cv = v & 7;
            cp16(base + r * (SAS * 2) + cv * 16,
                 A + (m0 + r) * C_ + k0 + cv * 8);
        }
        #pragma unroll
        for (int it = 0; it < 4; it++) {
            int v = it * 256 + tid;
            int r = v >> 3, cv = v & 7;
            cp16(base + A_B + r * (SAS * 2) + cv * 16,
                 w + (size_t)(n0 + r) * C_ + k0 + cv * 8);
        }
        cp_commit();
    };

    load_chunk(0, 0);
    load_chunk(1, 1);

    for (int kc = 0; kc < NKC; kc++) {
        if (kc < NKC - 1) cp_wait<1>();
        else              cp_wait<0>();
        __syncthreads();
        if (kc + 2 < NKC) load_chunk(kc + 2, (kc + 2) % NSTG);

        uint32_t base = sbase + (kc % NSTG) * STAGE_B;
        uint32_t aB = base, bB = base + A_B;

        #pragma unroll
        for (int ks = 0; ks < KCH / 16; ks++) {
            int kk = ks * 16;
            uint32_t a[2][4], b[4][4];
            #pragma unroll
            for (int i = 0; i < 2; i++)
                ldm_x4(a[i], aB + (wm + i * 16 + arow) * (SAS * 2) + (kk + acolo) * 2);
            #pragma unroll
            for (int p = 0; p < 4; p++)
                ldm_x4(b[p], bB + (wn + p * 16 + brow_in) * (SAS * 2) + (kk + bcolo) * 2);
            #pragma unroll
            for (int i = 0; i < 2; i++)
                #pragma unroll
                for (int j = 0; j < 8; j++) {
                    int p = j >> 1, o = (j & 1) * 2;
                    mma16816(acc[i][j], a[i], b[p][o], b[p][o + 1]);
                }
        }
    }
    __syncthreads();   // done with stage buffers; reuse as staging

    if (outF) {
        float* sD = reinterpret_cast<float*>(sm);
        #pragma unroll
        for (int i = 0; i < 2; i++) {
            int row = wm + i * 16 + gID;
            #pragma unroll
            for (int j = 0; j < 8; j++) {
                int col = wn + j * 8 + tig * 2;
                *reinterpret_cast<float2*>(&sD[row * SDF + col]) =
                    make_float2(acc[i][j][0], acc[i][j][1]);
                *reinterpret_cast<float2*>(&sD[(row + 8) * SDF + col]) =
                    make_float2(acc[i][j][2], acc[i][j][3]);
            }
        }
        __syncthreads();
        #pragma unroll
        for (int it = 0; it < 16; it++) {
            int idx = it * 256 + tid;
            int row = idx >> 5, seg = idx & 31;
            float4 v = *reinterpret_cast<float4*>(&sD[row * SDF + seg * 4]);
            *reinterpret_cast<float4*>(&outF[(m0 + row) * C_ + n0 + seg * 4]) = v;
        }
    } else {
        bool sig = (z == sig_z);
        __half* sD = sm;
        #pragma unroll
        for (int i = 0; i < 2; i++) {
            int row = wm + i * 16 + gID;
            #pragma unroll
            for (int j = 0; j < 8; j++) {
                int col = wn + j * 8 + tig * 2;
                float v0 = acc[i][j][0], v1 = acc[i][j][1];
                float v2 = acc[i][j][2], v3 = acc[i][j][3];
                if (sig) {
                    v0 = 1.0f / (1.0f + __expf(-v0));
                    v1 = 1.0f / (1.0f + __expf(-v1));
                    v2 = 1.0f / (1.0f + __expf(-v2));
                    v3 = 1.0f / (1.0f + __expf(-v3));
                }
                *reinterpret_cast<__half2*>(&sD[row * SDS + col]) =
                    __floats2half2_rn(v0, v1);
                *reinterpret_cast<__half2*>(&sD[(row + 8) * SDS + col]) =
                    __floats2half2_rn(v2, v3);
            }
        }
        __syncthreads();
        __half* oh = outH + (size_t)z * MC_;
        #pragma unroll
        for (int it = 0; it < 8; it++) {
            int idx = it * 256 + tid;
            int row = idx >> 4, seg = idx & 15;
            uint4 v = *reinterpret_cast<uint4*>(&sD[row * SDS + seg * 8]);
            *reinterpret_cast<uint4*>(&oh[(m0 + row) * C_ + n0 + seg * 8]) = v;
        }

        // ---- fused 32-step segment scans for k (z == 0) ----
        // m-tile == 128 timesteps == 4 segments; thread handles 2.
        if (z == 0 && td) {
            int ch = tid & 127, half = tid >> 7;
            int m0i = (int)m0;
            int b  = m0i >> 14;             // / N_
            int jc = (m0i & (N_ - 1)) >> 7; // m-tile index within batch
            float rr = fmaxf(td[n0 + ch], 0.f);
            float d  = __expf(-rr);
            #pragma unroll
            for (int sgi = 0; sgi < 2; sgi++) {
                int sg = half * 2 + sgi;
                float s = 0.f;
                #pragma unroll 8
                for (int i = 0; i < SEG; i++)
                    s = fmaf(s, d, __half2float(sD[(sg * SEG + i) * SDS + ch]));
                g_e[((size_t)((b * NC_ + jc) * 4 + sg)) * C_ + n0 + ch] = s;
            }
        }
    }
}

// ============================================================
// 3) Carry propagation over 512 segments, 32-wide batched loads
// ============================================================
__global__ __launch_bounds__(256) void scan_carry_kernel(const float* __restrict__ td) {
    int b = blockIdx.x, c = threadIdx.x;
    float r  = fmaxf(td[c], 0.f);
    float dS = expf(-r * (float)SEG);
    float cy = 0.f;
    for (int jb = 0; jb < NSG; jb += 32) {
        float e[32];
        #pragma unroll
        for (int u = 0; u < 32; u++) e[u] = g_e[(size_t)(b * NSG + jb + u) * C_ + c];
        #pragma unroll
        for (int u = 0; u < 32; u++) {
            g_carry[(size_t)(b * NSG + jb + u) * C_ + c] = cy;
            cy = fmaf(dS, cy, e[u]);
        }
    }
}

// ============================================================
// 4) Scan pass 2 + y = r*(s+v) -> fp16.  32-step segments.
//    grid (NSG/4, B_), 256 thr: 4 segments x 64 thr x 4 ch.
// ============================================================
__global__ __launch_bounds__(256) void scan2_kernel(const float* __restrict__ td) {
    int sub = threadIdx.x >> 6, t = threadIdx.x & 63;
    int j = blockIdx.x * 4 + sub, b = blockIdx.y;   // segment index 0..511
    int c0 = t * 4;
    float4 tdv = *reinterpret_cast<const float4*>(td + c0);
    float dx = expf(-fmaxf(tdv.x, 0.f)), dy = expf(-fmaxf(tdv.y, 0.f));
    float dz = expf(-fmaxf(tdv.z, 0.f)), dw = expf(-fmaxf(tdv.w, 0.f));
    size_t base = ((size_t)(b * N_ + j * SEG)) * C_ + c0;
    float4 s = reinterpret_cast<const float4*>(g_carry + (size_t)(b * NSG + j) * C_)[t];
    #pragma unroll 8
    for (int i = 0; i < SEG; i++) {
        size_t off = base + (size_t)i * C_;
        uint2 kraw = *reinterpret_cast<const uint2*>(&g_kvr[off]);
        uint2 vraw = *reinterpret_cast<const uint2*>(&g_kvr[MC_ + off]);
        uint2 rraw = *reinterpret_cast<const uint2*>(&g_kvr[2 * MC_ + off]);
        __half2 k01 = *reinterpret_cast<__half2*>(&kraw.x);
        __half2 k23 = *reinterpret_cast<__half2*>(&kraw.y);
        __half2 v01 = *reinterpret_cast<__half2*>(&vraw.x);
        __half2 v23 = *reinterpret_cast<__half2*>(&vraw.y);
        __half2 r01 = *reinterpret_cast<__half2*>(&rraw.x);
        __half2 r23 = *reinterpret_cast<__half2*>(&rraw.y);
        s.x = fmaf(s.x, dx, __low2float(k01));
        s.y = fmaf(s.y, dy, __high2float(k01));
        s.z = fmaf(s.z, dz, __low2float(k23));
        s.w = fmaf(s.w, dw, __high2float(k23));
        float y0 = __low2float(r01)  * (s.x + __low2float(v01));
        float y1 = __high2float(r01) * (s.y + __high2float(v01));
        float y2 = __low2float(r23)  * (s.z + __low2float(v23));
        float y3 = __high2float(r23) * (s.w + __high2float(v23));
        union { __half2 h2[2]; uint2 u; } Y;
        Y.h2[0] = __floats2half2_rn(y0, y1);
        Y.h2[1] = __floats2half2_rn(y2, y3);
        *reinterpret_cast<uint2*>(&g_ya[off]) = Y.u;
    }
}

// ============================================================
// launch
// ============================================================
extern "C" void kernel_launch(void* const* d_in, const int* in_sizes, int n_in,
                              void* d_out, int out_size) {
    const float* x   = (const float*)d_in[0];
    const float* td  = (const float*)d_in[1];
    const float* Wk  = (const float*)d_in[2];
    const float* Wv  = (const float*)d_in[3];
    const float* Wr  = (const float*)d_in[4];
    const float* Wo  = (const float*)d_in[5];
    const float* lnw = (const float*)d_in[6];
    const float* lnb = (const float*)d_in[7];
    float* out = (float*)d_out;

    __half *xa, *ya, *Wa, *Woa, *kvr;
    cudaGetSymbolAddress((void**)&xa,  g_xa);
    cudaGetSymbolAddress((void**)&ya,  g_ya);
    cudaGetSymbolAddress((void**)&Wa,  g_Wa);
    cudaGetSymbolAddress((void**)&Woa, g_Woa);
    cudaGetSymbolAddress((void**)&kvr, g_kvr);

    cudaFuncSetAttribute(mma_gemm_kernel,
                         cudaFuncAttributeMaxDynamicSharedMemorySize, SMEM_REQ);

    prep_kernel<<<M_ / 8 + 1024, 256>>>(x, lnw, lnb, Wk, Wv, Wr, Wo);
    // z=0 -> k (+fused segment scans), z=1 -> v, z=2 -> sigmoid(r)
    mma_gemm_kernel<<<dim3((C_ / BN) * 3, M_ / BM), 256, SMEM_REQ>>>(
        xa, Wa, nullptr, kvr, 3, 2, td);
    scan_carry_kernel<<<B_, 256>>>(td);
    scan2_kernel<<<dim3(NSG / 4, B_), 256>>>(td);
    // output GEMM -> fp32
    mma_gemm_kernel<<<dim3(C_ / BN, M_ / BM), 256, SMEM_REQ>>>(
        ya, Woa, out, nullptr, 1, -1, nullptr);
}